// round 1
// baseline (speedup 1.0000x reference)
#include <cuda_runtime.h>
#include <math.h>

#define NB 20000
#define HD 256
#define NL 4
#define TWO_N (2*NB)

// ---------------- device scratch (static, no allocation) ----------------
__device__ float g_h  [(size_t)TWO_N * HD];        // node features [2N,256]   41 MB
__device__ float g_P  [(size_t)TWO_N * 4 * HD];    // projections  [2N,1024]  164 MB
__device__ float g_agg[(size_t)TWO_N * HD];        // aggregated   [2N,256]    41 MB
__device__ float g_W  [(size_t)NL * 2 * HD * 4 * HD]; // packed proj weights  8.4 MB
__device__ float g_hm [HD];                        // column-mean accumulator

__device__ __forceinline__ float gelu_exact(float x) {
    return 0.5f * x * (1.0f + erff(x * 0.70710678118654752f));
}

// ---------------- pack projection weights -------------------------------
// g_W[l][half][k][c] with c in 4 blocks of 256: [A_chain | B_chain | A_cross | B_cross]
// chain type = half (0:power, 1:comm); cross type = 2.
__global__ void build_w(const float* __restrict__ msg_w) {
    int idx = blockIdx.x * blockDim.x + threadIdx.x;
    int total = NL * 2 * HD * 1024;
    if (idx >= total) return;
    int c  = idx & 1023;
    int r  = idx >> 10;
    int k  = r & 255;
    int lh = r >> 8;
    int half = lh & 1;
    int l    = lh >> 1;
    int blk = c >> 8;
    int cc  = c & 255;
    int t  = (blk < 2) ? half : 2;
    int kk = (blk & 1) ? (HD + k) : k;
    g_W[idx] = msg_w[(((size_t)(l * 3 + t) * 512) + kk) * HD + cc];
}

// ---------------- encoders ----------------------------------------------
__global__ void encode(const float* __restrict__ ex, const float* __restrict__ cx,
                       const float* __restrict__ Wew, const float* __restrict__ Web,
                       const float* __restrict__ Wcw, const float* __restrict__ Wcb) {
    int idx = blockIdx.x * blockDim.x + threadIdx.x;
    if (idx >= TWO_N * HD) return;
    int c = idx & 255;
    int g = idx >> 8;
    float v;
    if (g < NB) {
        const float* x = ex + (size_t)g * 5;
        v = Web[c];
        #pragma unroll
        for (int j = 0; j < 5; j++) v += x[j] * Wew[j * HD + c];
    } else {
        const float* x = cx + (size_t)(g - NB) * 3;
        v = Wcb[c];
        #pragma unroll
        for (int j = 0; j < 3; j++) v += x[j] * Wcw[j * HD + c];
    }
    g_h[idx] = v;
}

// ---------------- projection GEMM: P = X @ W (per half) ------------------
// M=20000 (per half), N=1024, K=256.  BM=BN=128, BK=8, 256 threads, 8x8/thread.
__global__ __launch_bounds__(256) void proj_gemm(int l) {
    const int BM = 128, BN = 128, BK = 8;
    int half = blockIdx.z;
    int row0 = blockIdx.y * BM;          // row within half
    int col0 = blockIdx.x * BN;
    const float* A = g_h + (size_t)half * NB * HD;
    const float* W = g_W + (size_t)(l * 2 + half) * HD * 1024;

    __shared__ float As[BK][BM + 4];     // transposed  (pad keeps 16B align: 132*4=528)
    __shared__ float Bs[BK][BN];

    int tid = threadIdx.x;
    int tx = tid & 15, ty = tid >> 4;

    float acc[8][8];
    #pragma unroll
    for (int i = 0; i < 8; i++)
        #pragma unroll
        for (int j = 0; j < 8; j++) acc[i][j] = 0.f;

    int a_row = tid >> 1, a_k0 = (tid & 1) * 4;   // 128x8 tile: 1 float4/thread
    int b_k   = tid >> 5, b_c  = (tid & 31) * 4;  // 8x128 tile: 1 float4/thread

    for (int k0 = 0; k0 < HD; k0 += BK) {
        int gr = row0 + a_row;
        float4 av = (gr < NB) ? *(const float4*)&A[(size_t)gr * HD + k0 + a_k0]
                              : make_float4(0.f, 0.f, 0.f, 0.f);
        As[a_k0 + 0][a_row] = av.x;
        As[a_k0 + 1][a_row] = av.y;
        As[a_k0 + 2][a_row] = av.z;
        As[a_k0 + 3][a_row] = av.w;
        *(float4*)&Bs[b_k][b_c] = *(const float4*)&W[(size_t)(k0 + b_k) * 1024 + col0 + b_c];
        __syncthreads();
        #pragma unroll
        for (int k = 0; k < BK; k++) {
            float a[8], b[8];
            float4 a0 = *(float4*)&As[k][ty * 8];
            float4 a1 = *(float4*)&As[k][ty * 8 + 4];
            a[0]=a0.x; a[1]=a0.y; a[2]=a0.z; a[3]=a0.w;
            a[4]=a1.x; a[5]=a1.y; a[6]=a1.z; a[7]=a1.w;
            float4 b0 = *(float4*)&Bs[k][tx * 8];
            float4 b1 = *(float4*)&Bs[k][tx * 8 + 4];
            b[0]=b0.x; b[1]=b0.y; b[2]=b0.z; b[3]=b0.w;
            b[4]=b1.x; b[5]=b1.y; b[6]=b1.z; b[7]=b1.w;
            #pragma unroll
            for (int i = 0; i < 8; i++)
                #pragma unroll
                for (int j = 0; j < 8; j++)
                    acc[i][j] = fmaf(a[i], b[j], acc[i][j]);
        }
        __syncthreads();
    }
    #pragma unroll
    for (int i = 0; i < 8; i++) {
        int r = row0 + ty * 8 + i;
        if (r >= NB) break;
        size_t base = ((size_t)(half * NB + r)) * 1024 + col0 + tx * 8;
        #pragma unroll
        for (int j = 0; j < 8; j += 4) {
            float4 v = make_float4(acc[i][j], acc[i][j+1], acc[i][j+2], acc[i][j+3]);
            *(float4*)&g_P[base + j] = v;
        }
    }
}

// ---------------- aggregation (pure elementwise, chain topology) ---------
__global__ void agg_kernel(int l, const float* __restrict__ msg_b) {
    int idx = blockIdx.x * blockDim.x + threadIdx.x;
    if (idx >= TWO_N * HD) return;
    int c = idx & 255;
    int g = idx >> 8;
    int half = (g >= NB) ? 1 : 0;
    int i = g - half * NB;
    int partner = half ? (g - NB) : (g + NB);
    float s = 0.f;
    int deg0 = 0;
    if (i > 0)      { s += g_P[(size_t)(g - 1) * 1024 + c]; deg0++; }
    if (i < NB - 1) { s += g_P[(size_t)(g + 1) * 1024 + c]; deg0++; }
    s += (float)deg0 * g_P[(size_t)g * 1024 + 256 + c];       // chain self (B)
    s += g_P[(size_t)partner * 1024 + 512 + c];               // cross neighbor (A2)
    s += g_P[(size_t)g * 1024 + 768 + c];                     // cross self (B2)
    s += (float)deg0 * msg_b[((size_t)l * 3 + half) * HD + c]
       + msg_b[((size_t)l * 3 + 2) * HD + c];
    g_agg[idx] = s / (float)(deg0 + 1);
}

// ---------------- update GEMM + LayerNorm + GeLU + residual --------------
// u = [h|agg] @ upd_w + ub ; LN ; gelu ; h += .   M=40000, N=256, K=512.
// BM=64, BN=256 (full row in block -> LN in epilogue), BK=16, 256 thr, 4x16/thread.
__global__ __launch_bounds__(256) void update_gemm(int l,
        const float* __restrict__ upd_w, const float* __restrict__ upd_b,
        const float* __restrict__ ln_g, const float* __restrict__ ln_b) {
    const int BM = 64, BK = 16;
    __shared__ float As[BK][BM + 4];   // 68*4=272B rows, 16B aligned
    __shared__ float Bs[BK][256];
    __shared__ float redS[BM][17];
    __shared__ float redQ[BM][17];
    __shared__ float muS[BM], rsS[BM];

    int tid = threadIdx.x;
    int tx = tid & 15, ty = tid >> 4;
    int row0 = blockIdx.x * BM;
    const float* W = upd_w + (size_t)l * 512 * HD;

    float acc[4][16];
    #pragma unroll
    for (int i = 0; i < 4; i++)
        #pragma unroll
        for (int j = 0; j < 16; j++) acc[i][j] = 0.f;

    int a_row = tid >> 2, a_k0 = (tid & 3) * 4;  // 64x16: 1 float4/thread

    for (int k0 = 0; k0 < 512; k0 += BK) {
        int gr = row0 + a_row;
        int kg = k0 + a_k0;
        const float* src = (kg < 256) ? &g_h[(size_t)gr * HD + kg]
                                      : &g_agg[(size_t)gr * HD + (kg - 256)];
        float4 av = *(const float4*)src;
        As[a_k0 + 0][a_row] = av.x;
        As[a_k0 + 1][a_row] = av.y;
        As[a_k0 + 2][a_row] = av.z;
        As[a_k0 + 3][a_row] = av.w;
        #pragma unroll
        for (int q = 0; q < 4; q++) {
            int f = tid + 256 * q;           // over 1024 float4s of 16x256 tile
            int kk = f >> 6, c4 = (f & 63) * 4;
            *(float4*)&Bs[kk][c4] = *(const float4*)&W[(size_t)(k0 + kk) * HD + c4];
        }
        __syncthreads();
        #pragma unroll
        for (int k = 0; k < BK; k++) {
            float4 a4 = *(float4*)&As[k][ty * 4];
            float a[4] = {a4.x, a4.y, a4.z, a4.w};
            float b[16];
            #pragma unroll
            for (int q = 0; q < 4; q++) {
                float4 bb = *(float4*)&Bs[k][tx * 16 + q * 4];
                b[q*4+0]=bb.x; b[q*4+1]=bb.y; b[q*4+2]=bb.z; b[q*4+3]=bb.w;
            }
            #pragma unroll
            for (int i = 0; i < 4; i++)
                #pragma unroll
                for (int j = 0; j < 16; j++)
                    acc[i][j] = fmaf(a[i], b[j], acc[i][j]);
        }
        __syncthreads();
    }

    // epilogue: +ub, LayerNorm stats, gelu, residual
    #pragma unroll
    for (int i = 0; i < 4; i++) {
        float s = 0.f, q = 0.f;
        #pragma unroll
        for (int j = 0; j < 16; j++) {
            float v = acc[i][j] + upd_b[(size_t)l * HD + tx * 16 + j];
            acc[i][j] = v;
            s += v; q += v * v;
        }
        redS[ty * 4 + i][tx] = s;
        redQ[ty * 4 + i][tx] = q;
    }
    __syncthreads();
    if (tid < BM) {
        float s = 0.f, q = 0.f;
        #pragma unroll
        for (int j = 0; j < 16; j++) { s += redS[tid][j]; q += redQ[tid][j]; }
        float mu  = s * (1.0f / HD);
        float var = q * (1.0f / HD) - mu * mu;
        muS[tid] = mu;
        rsS[tid] = rsqrtf(var + 1e-5f);
    }
    __syncthreads();
    #pragma unroll
    for (int i = 0; i < 4; i++) {
        int r  = ty * 4 + i;
        int gr = row0 + r;
        float mu = muS[r], rs = rsS[r];
        #pragma unroll
        for (int j = 0; j < 16; j++) {
            int col = tx * 16 + j;
            float un = (acc[i][j] - mu) * rs * ln_g[(size_t)l * HD + col]
                     + ln_b[(size_t)l * HD + col];
            size_t o = (size_t)gr * HD + col;
            g_h[o] = g_h[o] + gelu_exact(un);
        }
    }
}

// ---------------- readout -----------------------------------------------
__global__ void zero_hm() { if (threadIdx.x < HD) g_hm[threadIdx.x] = 0.f; }

__global__ void colmean() {
    int c = threadIdx.x;            // 256 threads, grid 100 blocks
    int r0 = blockIdx.x * 200;
    float s = 0.f;
    for (int r = r0; r < r0 + 200; r++) s += g_h[(size_t)r * HD + c];
    atomicAdd(&g_hm[c], s);
}

__global__ void decoder(const float* __restrict__ dec1_w, const float* __restrict__ dec1_b,
                        const float* __restrict__ dec2_w, const float* __restrict__ dec2_b,
                        const float* __restrict__ Kp, const float* __restrict__ tau,
                        const float* __restrict__ tau_max, const float* __restrict__ lam,
                        float* __restrict__ out) {
    __shared__ float hm[HD], z[HD], red[64];
    int t = threadIdx.x;
    hm[t] = g_hm[t] * (1.0f / NB);
    __syncthreads();
    float acc = dec1_b[t];
    for (int k = 0; k < HD; k++) acc += hm[k] * dec1_w[k * HD + t];
    z[t] = gelu_exact(acc);
    __syncthreads();
    if (t < 128) {
        float a = dec2_b[t];
        for (int k = 0; k < HD; k++) a += z[k] * dec2_w[k * 128 + t];
        out[t] = a;                        // u
    }
    if (t < 64) {
        red[t] = Kp[t] * tau[t] / tau_max[t];
        out[129 + t] = Kp[t];              // K
    }
    __syncthreads();
    if (t == 0) {
        float s = 0.f;
        for (int i = 0; i < 64; i++) s += red[i];
        out[128] = fabsf(lam[0]) - s;      // rho
    }
}

// ---------------- launch --------------------------------------------------
extern "C" void kernel_launch(void* const* d_in, const int* in_sizes, int n_in,
                              void* d_out, int out_size) {
    const float* energy_x     = (const float*)d_in[0];
    const float* comm_x       = (const float*)d_in[1];
    const float* tau          = (const float*)d_in[2];
    const float* tau_max      = (const float*)d_in[3];
    const float* lambda_min_0 = (const float*)d_in[4];
    const float* We_w         = (const float*)d_in[5];
    const float* We_b         = (const float*)d_in[6];
    const float* Wc_w         = (const float*)d_in[7];
    const float* Wc_b         = (const float*)d_in[8];
    const float* msg_w        = (const float*)d_in[9];
    const float* msg_b        = (const float*)d_in[10];
    const float* upd_w        = (const float*)d_in[11];
    const float* upd_b        = (const float*)d_in[12];
    const float* ln_g         = (const float*)d_in[13];
    const float* ln_b         = (const float*)d_in[14];
    const float* dec1_w       = (const float*)d_in[15];
    const float* dec1_b       = (const float*)d_in[16];
    const float* dec2_w       = (const float*)d_in[17];
    const float* dec2_b       = (const float*)d_in[18];
    const float* K_param      = (const float*)d_in[19];
    float* out = (float*)d_out;

    build_w<<<(NL * 2 * HD * 1024 + 255) / 256, 256>>>(msg_w);
    encode<<<(TWO_N * HD + 255) / 256, 256>>>(energy_x, comm_x, We_w, We_b, Wc_w, Wc_b);

    for (int l = 0; l < NL; l++) {
        dim3 gp(1024 / 128, (NB + 127) / 128, 2);   // (8, 157, 2)
        proj_gemm<<<gp, 256>>>(l);
        agg_kernel<<<(TWO_N * HD + 255) / 256, 256>>>(l, msg_b);
        update_gemm<<<TWO_N / 64, 256>>>(l, upd_w, upd_b, ln_g, ln_b);
    }

    zero_hm<<<1, 256>>>();
    colmean<<<100, 256>>>();
    decoder<<<1, 256>>>(dec1_w, dec1_b, dec2_w, dec2_b,
                        K_param, tau, tau_max, lambda_min_0, out);
}

// round 2
// speedup vs baseline: 3.2471x; 3.2471x over previous
#include <cuda_runtime.h>
#include <math.h>

#define NB 20000
#define HD 256
#define NL 4
#define TWO_N (2*NB)
#define NWC 768

// ---------------- device scratch ----------------
__device__ float g_h  [(size_t)TWO_N * HD];       // node features     41 MB
__device__ float g_T  [(size_t)TWO_N * NWC];      // fused projections 123 MB
__device__ float g_Wc [(size_t)NL * 2 * HD * NWC];// folded weights [S|N|X]
__device__ float g_We [(size_t)NL * 2 * HD * HD]; // endpoint matrices
__device__ float g_bias [NL * 2 * HD];
__device__ float g_bias2[NL * 2 * HD];
__device__ float g_hm [HD];

__device__ __forceinline__ float gelu_exact(float x) {
    return 0.5f * x * (1.0f + erff(x * 0.70710678118654752f));
}
__device__ __forceinline__ float4 ld4(const float* p) { return *(const float4*)p; }
__device__ __forceinline__ float4 f4z() { return make_float4(0.f,0.f,0.f,0.f); }
__device__ __forceinline__ float4 f4add(float4 a, float4 b) {
    return make_float4(a.x+b.x, a.y+b.y, a.z+b.z, a.w+b.w);
}
__device__ __forceinline__ float4 f4fma(float s, float4 a, float4 b) {
    return make_float4(fmaf(s,a.x,b.x), fmaf(s,a.y,b.y), fmaf(s,a.z,b.z), fmaf(s,a.w,b.w));
}

// ---------------- encoders ----------------
__global__ void encode(const float* __restrict__ ex, const float* __restrict__ cx,
                       const float* __restrict__ Wew, const float* __restrict__ Web,
                       const float* __restrict__ Wcw, const float* __restrict__ Wcb) {
    int idx = blockIdx.x * blockDim.x + threadIdx.x;
    if (idx >= TWO_N * HD) return;
    int c = idx & 255;
    int g = idx >> 8;
    float v;
    if (g < NB) {
        const float* x = ex + (size_t)g * 5;
        v = Web[c];
        #pragma unroll
        for (int j = 0; j < 5; j++) v += x[j] * Wew[j * HD + c];
    } else {
        const float* x = cx + (size_t)(g - NB) * 3;
        v = Wcb[c];
        #pragma unroll
        for (int j = 0; j < 3; j++) v += x[j] * Wcw[j * HD + c];
    }
    g_h[idx] = v;
}

// ---------------- weight folding: Wc=[S|N|X], We=endpoint ----------------
// sec0: S = U1 + (2*B_h + B2)@U2 /3
// sec1: N = A_h@U2 /3
// sec2: X = A2 @U2 /3
// sec3: E = U1 + (B_h + B2)@U2 /2
__global__ __launch_bounds__(256, 2) void gemm_pre(const float* __restrict__ msg_w,
                                                   const float* __restrict__ upd_w) {
    int cb = blockIdx.x;           // 0..7
    int rb = blockIdx.y;           // 0..1
    int lh = blockIdx.z;           // 0..7
    int l = lh >> 1, h = lh & 1;
    int sec = cb >> 1;
    int col0 = (cb & 1) * 128;
    int row0 = rb * 128;
    const float* mh = msg_w + (size_t)(l*3 + h) * 512 * HD;
    const float* m2 = msg_w + (size_t)(l*3 + 2) * 512 * HD;
    const float* U1 = upd_w + (size_t)l * 512 * HD;
    const float* U2 = U1 + (size_t)HD * HD;
    const float* P1; const float* P2; float w1, w2, scale; int addU1;
    if (sec == 0)      { P1 = mh + HD*HD; w1 = 2.f; P2 = m2 + HD*HD; w2 = 1.f; scale = 1.f/3.f; addU1 = 1; }
    else if (sec == 1) { P1 = mh;          w1 = 1.f; P2 = 0;          w2 = 0.f; scale = 1.f/3.f; addU1 = 0; }
    else if (sec == 2) { P1 = m2;          w1 = 1.f; P2 = 0;          w2 = 0.f; scale = 1.f/3.f; addU1 = 0; }
    else               { P1 = mh + HD*HD; w1 = 1.f; P2 = m2 + HD*HD; w2 = 1.f; scale = 0.5f;    addU1 = 1; }

    __shared__ float As[2][16][132];
    __shared__ float Bs[2][16][128];
    int tid = threadIdx.x;
    int tx = tid & 15, ty = tid >> 4;
    int ar = tid >> 2, ak = (tid & 3) * 4;
    int bk = tid >> 5, bn = (tid & 31) * 4;

    float acc[8][8];
    #pragma unroll
    for (int i = 0; i < 8; i++)
        #pragma unroll
        for (int j = 0; j < 8; j++) acc[i][j] = 0.f;

    float4 a0v, a1v, b0v, b1v;
    {
        int r0 = row0 + ar, r1 = row0 + ar + 64;
        a0v = ld4(&P1[(size_t)r0*HD + ak]);
        a1v = ld4(&P1[(size_t)r1*HD + ak]);
        if (P2) { a0v = f4fma(w2/w1, ld4(&P2[(size_t)r0*HD + ak]), a0v);
                  a1v = f4fma(w2/w1, ld4(&P2[(size_t)r1*HD + ak]), a1v); }
        b0v = ld4(&U2[(size_t)bk*HD + col0 + bn]);
        b1v = ld4(&U2[(size_t)(bk+8)*HD + col0 + bn]);
    }
    As[0][ak+0][ar]=a0v.x; As[0][ak+1][ar]=a0v.y; As[0][ak+2][ar]=a0v.z; As[0][ak+3][ar]=a0v.w;
    As[0][ak+0][64+ar]=a1v.x; As[0][ak+1][64+ar]=a1v.y; As[0][ak+2][64+ar]=a1v.z; As[0][ak+3][64+ar]=a1v.w;
    *(float4*)&Bs[0][bk][bn] = b0v; *(float4*)&Bs[0][bk+8][bn] = b1v;
    __syncthreads();

    int buf = 0;
    #pragma unroll 1
    for (int t = 0; t < 16; t++) {
        if (t < 15) {
            int k0 = (t + 1) * 16;
            int r0 = row0 + ar, r1 = row0 + ar + 64;
            a0v = ld4(&P1[(size_t)r0*HD + k0 + ak]);
            a1v = ld4(&P1[(size_t)r1*HD + k0 + ak]);
            if (P2) { a0v = f4fma(w2/w1, ld4(&P2[(size_t)r0*HD + k0 + ak]), a0v);
                      a1v = f4fma(w2/w1, ld4(&P2[(size_t)r1*HD + k0 + ak]), a1v); }
            b0v = ld4(&U2[(size_t)(k0+bk)*HD + col0 + bn]);
            b1v = ld4(&U2[(size_t)(k0+bk+8)*HD + col0 + bn]);
        }
        #pragma unroll
        for (int k = 0; k < 16; k++) {
            float4 pa0 = *(float4*)&As[buf][k][ty*4];
            float4 pa1 = *(float4*)&As[buf][k][64 + ty*4];
            float4 pb0 = *(float4*)&Bs[buf][k][tx*4];
            float4 pb1 = *(float4*)&Bs[buf][k][64 + tx*4];
            float aa[8] = {pa0.x,pa0.y,pa0.z,pa0.w,pa1.x,pa1.y,pa1.z,pa1.w};
            float bb[8] = {pb0.x,pb0.y,pb0.z,pb0.w,pb1.x,pb1.y,pb1.z,pb1.w};
            #pragma unroll
            for (int i = 0; i < 8; i++)
                #pragma unroll
                for (int j = 0; j < 8; j++)
                    acc[i][j] = fmaf(aa[i], bb[j], acc[i][j]);
        }
        if (t < 15) {
            int nb2 = buf ^ 1;
            As[nb2][ak+0][ar]=a0v.x; As[nb2][ak+1][ar]=a0v.y; As[nb2][ak+2][ar]=a0v.z; As[nb2][ak+3][ar]=a0v.w;
            As[nb2][ak+0][64+ar]=a1v.x; As[nb2][ak+1][64+ar]=a1v.y; As[nb2][ak+2][64+ar]=a1v.z; As[nb2][ak+3][64+ar]=a1v.w;
            *(float4*)&Bs[nb2][bk][bn] = b0v; *(float4*)&Bs[nb2][bk+8][bn] = b1v;
        }
        __syncthreads();
        buf ^= 1;
    }

    float sc = w1 * scale;   // fold w1 back (loads were P1 + (w2/w1)P2)
    #pragma unroll
    for (int ih = 0; ih < 2; ih++)
        #pragma unroll
        for (int ii = 0; ii < 4; ii++) {
            int r = row0 + ih*64 + ty*4 + ii;
            #pragma unroll
            for (int jh = 0; jh < 2; jh++) {
                int c = col0 + jh*64 + tx*4;
                float4 v;
                v.x = acc[ih*4+ii][jh*4+0] * sc;
                v.y = acc[ih*4+ii][jh*4+1] * sc;
                v.z = acc[ih*4+ii][jh*4+2] * sc;
                v.w = acc[ih*4+ii][jh*4+3] * sc;
                if (addU1) v = f4add(v, ld4(&U1[(size_t)r*HD + c]));
                if (sec < 3)
                    *(float4*)&g_Wc[(size_t)lh*HD*NWC + (size_t)r*NWC + sec*HD + c] = v;
                else
                    *(float4*)&g_We[(size_t)lh*HD*HD + (size_t)r*HD + c] = v;
            }
        }
}

// ---------------- bias folding ----------------
__global__ void bias_kernel(const float* __restrict__ msg_b,
                            const float* __restrict__ upd_w,
                            const float* __restrict__ upd_b) {
    int lh = blockIdx.x; int l = lh >> 1, h = lh & 1;
    int c = threadIdx.x;
    __shared__ float v1[HD], v2[HD];
    float mbh = msg_b[(l*3 + h)*HD + c];
    float mb2 = msg_b[(l*3 + 2)*HD + c];
    v1[c] = 2.f*mbh + mb2;
    v2[c] = mbh + mb2;
    __syncthreads();
    const float* U2 = upd_w + ((size_t)l*512 + HD) * HD;
    float s1 = 0.f, s2 = 0.f;
    for (int k = 0; k < HD; k++) {
        float u = U2[(size_t)k*HD + c];
        s1 += v1[k]*u; s2 += v2[k]*u;
    }
    g_bias [lh*HD + c] = s1*(1.f/3.f) + upd_b[l*HD + c];
    g_bias2[lh*HD + c] = s2*0.5f     + upd_b[l*HD + c];
}

// ---------------- main GEMM: T = X @ Wc  (M=20000/half, N=768, K=256) ------
__global__ __launch_bounds__(256, 2) void gemm_main(int l) {
    int half = blockIdx.z;
    int row0 = blockIdx.y * 128;
    int col0 = blockIdx.x * 128;
    const float* A = g_h + (size_t)half * NB * HD;
    const float* B = g_Wc + (size_t)(l*2 + half) * HD * NWC;

    __shared__ float As[2][16][132];
    __shared__ float Bs[2][16][128];
    int tid = threadIdx.x;
    int tx = tid & 15, ty = tid >> 4;
    int ar = tid >> 2, ak = (tid & 3) * 4;
    int bk = tid >> 5, bn = (tid & 31) * 4;

    int r0g = row0 + ar, r1g = row0 + ar + 64;
    bool p0 = r0g < NB, p1 = r1g < NB;

    float acc[8][8];
    #pragma unroll
    for (int i = 0; i < 8; i++)
        #pragma unroll
        for (int j = 0; j < 8; j++) acc[i][j] = 0.f;

    float4 a0v, a1v, b0v, b1v;
    a0v = p0 ? ld4(&A[(size_t)r0g*HD + ak]) : f4z();
    a1v = p1 ? ld4(&A[(size_t)r1g*HD + ak]) : f4z();
    b0v = ld4(&B[(size_t)bk*NWC + col0 + bn]);
    b1v = ld4(&B[(size_t)(bk+8)*NWC + col0 + bn]);
    As[0][ak+0][ar]=a0v.x; As[0][ak+1][ar]=a0v.y; As[0][ak+2][ar]=a0v.z; As[0][ak+3][ar]=a0v.w;
    As[0][ak+0][64+ar]=a1v.x; As[0][ak+1][64+ar]=a1v.y; As[0][ak+2][64+ar]=a1v.z; As[0][ak+3][64+ar]=a1v.w;
    *(float4*)&Bs[0][bk][bn] = b0v; *(float4*)&Bs[0][bk+8][bn] = b1v;
    __syncthreads();

    int buf = 0;
    #pragma unroll 1
    for (int t = 0; t < 16; t++) {
        if (t < 15) {
            int k0 = (t + 1) * 16;
            a0v = p0 ? ld4(&A[(size_t)r0g*HD + k0 + ak]) : f4z();
            a1v = p1 ? ld4(&A[(size_t)r1g*HD + k0 + ak]) : f4z();
            b0v = ld4(&B[(size_t)(k0+bk)*NWC + col0 + bn]);
            b1v = ld4(&B[(size_t)(k0+bk+8)*NWC + col0 + bn]);
        }
        #pragma unroll
        for (int k = 0; k < 16; k++) {
            float4 pa0 = *(float4*)&As[buf][k][ty*4];
            float4 pa1 = *(float4*)&As[buf][k][64 + ty*4];
            float4 pb0 = *(float4*)&Bs[buf][k][tx*4];
            float4 pb1 = *(float4*)&Bs[buf][k][64 + tx*4];
            float aa[8] = {pa0.x,pa0.y,pa0.z,pa0.w,pa1.x,pa1.y,pa1.z,pa1.w};
            float bb[8] = {pb0.x,pb0.y,pb0.z,pb0.w,pb1.x,pb1.y,pb1.z,pb1.w};
            #pragma unroll
            for (int i = 0; i < 8; i++)
                #pragma unroll
                for (int j = 0; j < 8; j++)
                    acc[i][j] = fmaf(aa[i], bb[j], acc[i][j]);
        }
        if (t < 15) {
            int nb2 = buf ^ 1;
            As[nb2][ak+0][ar]=a0v.x; As[nb2][ak+1][ar]=a0v.y; As[nb2][ak+2][ar]=a0v.z; As[nb2][ak+3][ar]=a0v.w;
            As[nb2][ak+0][64+ar]=a1v.x; As[nb2][ak+1][64+ar]=a1v.y; As[nb2][ak+2][64+ar]=a1v.z; As[nb2][ak+3][64+ar]=a1v.w;
            *(float4*)&Bs[nb2][bk][bn] = b0v; *(float4*)&Bs[nb2][bk+8][bn] = b1v;
        }
        __syncthreads();
        buf ^= 1;
    }

    #pragma unroll
    for (int ih = 0; ih < 2; ih++)
        #pragma unroll
        for (int ii = 0; ii < 4; ii++) {
            int r = row0 + ih*64 + ty*4 + ii;
            if (r >= NB) continue;
            size_t base = ((size_t)(half*NB + r)) * NWC + col0;
            float4 v0 = make_float4(acc[ih*4+ii][0], acc[ih*4+ii][1], acc[ih*4+ii][2], acc[ih*4+ii][3]);
            float4 v1 = make_float4(acc[ih*4+ii][4], acc[ih*4+ii][5], acc[ih*4+ii][6], acc[ih*4+ii][7]);
            *(float4*)&g_T[base + tx*4]      = v0;
            *(float4*)&g_T[base + 64 + tx*4] = v1;
        }
}

// ---------------- combine: u-sum + LN + GeLU + residual -------------------
__global__ __launch_bounds__(256) void combine(int l,
        const float* __restrict__ ln_g, const float* __restrict__ ln_b) {
    int node = blockIdx.x * 8 + (threadIdx.x >> 5);
    int lane = threadIdx.x & 31;
    int half = node >= NB ? 1 : 0;
    int i = node - half * NB;
    int p = half ? node - NB : node + NB;
    int c0 = lane * 4, c1 = 128 + lane * 4;
    float4 u0, u1;

    if (i > 0 && i < NB - 1) {
        const float* tS  = g_T + (size_t)node * NWC;
        const float* tNm = g_T + (size_t)(node - 1) * NWC + 256;
        const float* tNp = g_T + (size_t)(node + 1) * NWC + 256;
        const float* tX  = g_T + (size_t)p * NWC + 512;
        const float* bi  = g_bias + (l*2 + half) * HD;
        u0 = f4add(f4add(ld4(tS+c0), ld4(tNm+c0)), f4add(ld4(tNp+c0), f4add(ld4(tX+c0), ld4(bi+c0))));
        u1 = f4add(f4add(ld4(tS+c1), ld4(tNm+c1)), f4add(ld4(tNp+c1), f4add(ld4(tX+c1), ld4(bi+c1))));
    } else {
        int nn = (i == 0) ? node + 1 : node - 1;
        const float* E  = g_We + (size_t)(l*2 + half) * HD * HD;
        const float* xg = g_h + (size_t)node * HD;
        float4 s0 = f4z(), s1 = f4z();
        #pragma unroll 4
        for (int k = 0; k < HD; k++) {
            float xv = xg[k];
            s0 = f4fma(xv, ld4(&E[(size_t)k*HD + c0]), s0);
            s1 = f4fma(xv, ld4(&E[(size_t)k*HD + c1]), s1);
        }
        const float* tN  = g_T + (size_t)nn * NWC + 256;
        const float* tX  = g_T + (size_t)p * NWC + 512;
        const float* bi2 = g_bias2 + (l*2 + half) * HD;
        u0 = f4add(s0, f4fma(1.5f, f4add(ld4(tN+c0), ld4(tX+c0)), ld4(bi2+c0)));
        u1 = f4add(s1, f4fma(1.5f, f4add(ld4(tN+c1), ld4(tX+c1)), ld4(bi2+c1)));
    }

    float s = u0.x+u0.y+u0.z+u0.w + u1.x+u1.y+u1.z+u1.w;
    float q = u0.x*u0.x+u0.y*u0.y+u0.z*u0.z+u0.w*u0.w
            + u1.x*u1.x+u1.y*u1.y+u1.z*u1.z+u1.w*u1.w;
    #pragma unroll
    for (int off = 16; off; off >>= 1) {
        s += __shfl_xor_sync(0xffffffff, s, off);
        q += __shfl_xor_sync(0xffffffff, q, off);
    }
    float mu = s * (1.f/HD);
    float rs = rsqrtf(q * (1.f/HD) - mu*mu + 1e-5f);

    const float* lg = ln_g + l*HD;
    const float* lb = ln_b + l*HD;
    float4 g0 = ld4(lg+c0), g1 = ld4(lg+c1);
    float4 b0 = ld4(lb+c0), b1 = ld4(lb+c1);
    size_t ho = (size_t)node * HD;
    float4 h0 = ld4(&g_h[ho+c0]), h1 = ld4(&g_h[ho+c1]);
    h0.x += gelu_exact((u0.x-mu)*rs*g0.x + b0.x);
    h0.y += gelu_exact((u0.y-mu)*rs*g0.y + b0.y);
    h0.z += gelu_exact((u0.z-mu)*rs*g0.z + b0.z);
    h0.w += gelu_exact((u0.w-mu)*rs*g0.w + b0.w);
    h1.x += gelu_exact((u1.x-mu)*rs*g1.x + b1.x);
    h1.y += gelu_exact((u1.y-mu)*rs*g1.y + b1.y);
    h1.z += gelu_exact((u1.z-mu)*rs*g1.z + b1.z);
    h1.w += gelu_exact((u1.w-mu)*rs*g1.w + b1.w);
    *(float4*)&g_h[ho+c0] = h0;
    *(float4*)&g_h[ho+c1] = h1;
}

// ---------------- readout ----------------
__global__ void zero_hm() { if (threadIdx.x < HD) g_hm[threadIdx.x] = 0.f; }

__global__ void colmean() {
    int c = threadIdx.x;
    int r0 = blockIdx.x * 200;
    float s = 0.f;
    for (int r = r0; r < r0 + 200; r++) s += g_h[(size_t)r * HD + c];
    atomicAdd(&g_hm[c], s);
}

__global__ void decoder(const float* __restrict__ dec1_w, const float* __restrict__ dec1_b,
                        const float* __restrict__ dec2_w, const float* __restrict__ dec2_b,
                        const float* __restrict__ Kp, const float* __restrict__ tau,
                        const float* __restrict__ tau_max, const float* __restrict__ lam,
                        float* __restrict__ out) {
    __shared__ float hm[HD], z[HD], red[64];
    int t = threadIdx.x;
    hm[t] = g_hm[t] * (1.0f / NB);
    __syncthreads();
    float acc = dec1_b[t];
    for (int k = 0; k < HD; k++) acc += hm[k] * dec1_w[k * HD + t];
    z[t] = gelu_exact(acc);
    __syncthreads();
    if (t < 128) {
        float a = dec2_b[t];
        for (int k = 0; k < HD; k++) a += z[k] * dec2_w[k * 128 + t];
        out[t] = a;
    }
    if (t < 64) {
        red[t] = Kp[t] * tau[t] / tau_max[t];
        out[129 + t] = Kp[t];
    }
    __syncthreads();
    if (t == 0) {
        float s = 0.f;
        for (int i = 0; i < 64; i++) s += red[i];
        out[128] = fabsf(lam[0]) - s;
    }
}

// ---------------- launch ----------------
extern "C" void kernel_launch(void* const* d_in, const int* in_sizes, int n_in,
                              void* d_out, int out_size) {
    const float* energy_x     = (const float*)d_in[0];
    const float* comm_x       = (const float*)d_in[1];
    const float* tau          = (const float*)d_in[2];
    const float* tau_max      = (const float*)d_in[3];
    const float* lambda_min_0 = (const float*)d_in[4];
    const float* We_w         = (const float*)d_in[5];
    const float* We_b         = (const float*)d_in[6];
    const float* Wc_w         = (const float*)d_in[7];
    const float* Wc_b         = (const float*)d_in[8];
    const float* msg_w        = (const float*)d_in[9];
    const float* msg_b        = (const float*)d_in[10];
    const float* upd_w        = (const float*)d_in[11];
    const float* upd_b        = (const float*)d_in[12];
    const float* ln_g         = (const float*)d_in[13];
    const float* ln_b         = (const float*)d_in[14];
    const float* dec1_w       = (const float*)d_in[15];
    const float* dec1_b       = (const float*)d_in[16];
    const float* dec2_w       = (const float*)d_in[17];
    const float* dec2_b       = (const float*)d_in[18];
    const float* K_param      = (const float*)d_in[19];
    float* out = (float*)d_out;

    gemm_pre<<<dim3(8, 2, 8), 256>>>(msg_w, upd_w);
    bias_kernel<<<8, 256>>>(msg_b, upd_w, upd_b);
    encode<<<(TWO_N * HD + 255) / 256, 256>>>(energy_x, comm_x, We_w, We_b, Wc_w, Wc_b);

    for (int l = 0; l < NL; l++) {
        gemm_main<<<dim3(6, (NB + 127) / 128, 2), 256>>>(l);
        combine<<<TWO_N / 8, 256>>>(l, ln_g, ln_b);
    }

    zero_hm<<<1, 256>>>();
    colmean<<<100, 256>>>();
    decoder<<<1, 256>>>(dec1_w, dec1_b, dec2_w, dec2_b,
                        K_param, tau, tau_max, lambda_min_0, out);
}

// round 4
// speedup vs baseline: 4.1501x; 1.2781x over previous
#include <cuda_runtime.h>
#include <cuda_bf16.h>
#include <math.h>
#include <stdint.h>

#define NB 20000
#define HD 256
#define NL 4
#define TWO_N (2*NB)
#define NWC 768

// ---------------- device scratch ----------------
__device__ float g_h  [(size_t)TWO_N * HD];
__device__ __nv_bfloat16 g_xh[(size_t)TWO_N * HD];
__device__ __nv_bfloat16 g_xl[(size_t)TWO_N * HD];
__device__ float g_T  [(size_t)TWO_N * NWC];
__device__ __nv_bfloat16 g_wth[(size_t)NL * 2 * NWC * HD];  // [lh][n][k]
__device__ __nv_bfloat16 g_wtl[(size_t)NL * 2 * NWC * HD];
__device__ float g_We [(size_t)NL * 2 * HD * HD];
__device__ float g_bias [NL * 2 * HD];
__device__ float g_bias2[NL * 2 * HD];
__device__ float g_hm [HD];

// ---------------- helpers ----------------
__device__ __forceinline__ float gelu_exact(float x) {
    return 0.5f * x * (1.0f + erff(x * 0.70710678118654752f));
}
__device__ __forceinline__ float4 ld4(const float* p) { return *(const float4*)p; }
__device__ __forceinline__ float4 f4z() { return make_float4(0.f,0.f,0.f,0.f); }
__device__ __forceinline__ float4 f4add(float4 a, float4 b) {
    return make_float4(a.x+b.x, a.y+b.y, a.z+b.z, a.w+b.w);
}
__device__ __forceinline__ float4 f4fma(float s, float4 a, float4 b) {
    return make_float4(fmaf(s,a.x,b.x), fmaf(s,a.y,b.y), fmaf(s,a.z,b.z), fmaf(s,a.w,b.w));
}
__device__ __forceinline__ uint32_t smem_u32(const void* p) {
    uint32_t a;
    asm("{ .reg .u64 t; cvta.to.shared.u64 t, %1; cvt.u32.u64 %0, t; }" : "=r"(a) : "l"(p));
    return a;
}
__device__ __forceinline__ void cpa16(uint32_t s, const void* g) {
    asm volatile("cp.async.cg.shared.global [%0], [%1], 16;" :: "r"(s), "l"(g));
}
__device__ __forceinline__ void st_split(size_t off, float4 v) {
    __nv_bfloat16 hx = __float2bfloat16(v.x), hy = __float2bfloat16(v.y);
    __nv_bfloat16 hz = __float2bfloat16(v.z), hw = __float2bfloat16(v.w);
    __nv_bfloat162* ph = (__nv_bfloat162*)&g_xh[off];
    ph[0] = __nv_bfloat162(hx, hy); ph[1] = __nv_bfloat162(hz, hw);
    __nv_bfloat162* pl = (__nv_bfloat162*)&g_xl[off];
    pl[0] = __nv_bfloat162(__float2bfloat16(v.x - __bfloat162float(hx)),
                           __float2bfloat16(v.y - __bfloat162float(hy)));
    pl[1] = __nv_bfloat162(__float2bfloat16(v.z - __bfloat162float(hz)),
                           __float2bfloat16(v.w - __bfloat162float(hw)));
}

#define MMA3(c, A, B) asm volatile( \
    "mma.sync.aligned.m16n8k16.row.col.f32.bf16.bf16.f32 " \
    "{%0,%1,%2,%3},{%4,%5,%6,%7},{%8,%9},{%0,%1,%2,%3};" \
    : "+f"(c[0]),"+f"(c[1]),"+f"(c[2]),"+f"(c[3]) \
    : "r"(A[0]),"r"(A[1]),"r"(A[2]),"r"(A[3]),"r"(B[0]),"r"(B[1]))

// ---------------- encoders ----------------
__global__ void encode(const float* __restrict__ ex, const float* __restrict__ cx,
                       const float* __restrict__ Wew, const float* __restrict__ Web,
                       const float* __restrict__ Wcw, const float* __restrict__ Wcb) {
    int idx = blockIdx.x * blockDim.x + threadIdx.x;
    if (idx >= TWO_N * HD / 4) return;
    int c = (idx & 63) * 4;
    int g = idx >> 6;
    float4 v;
    if (g < NB) {
        const float* x = ex + (size_t)g * 5;
        v = ld4(&Web[c]);
        #pragma unroll
        for (int j = 0; j < 5; j++) v = f4fma(x[j], ld4(&Wew[j * HD + c]), v);
    } else {
        const float* x = cx + (size_t)(g - NB) * 3;
        v = ld4(&Wcb[c]);
        #pragma unroll
        for (int j = 0; j < 3; j++) v = f4fma(x[j], ld4(&Wcw[j * HD + c]), v);
    }
    size_t off = (size_t)g * HD + c;
    *(float4*)&g_h[off] = v;
    st_split(off, v);
}

// ---------------- weight folding ----------------
// sec0: S = U1 + (2*B_h + B2)@U2 /3 ; sec1: N = A_h@U2 /3 ; sec2: X = A2@U2 /3
// sec3: E = U1 + (B_h + B2)@U2 /2  (endpoint, fp32)
__global__ __launch_bounds__(256, 2) void gemm_pre(const float* __restrict__ msg_w,
                                                   const float* __restrict__ upd_w) {
    int cb = blockIdx.x, rb = blockIdx.y, lh = blockIdx.z;
    int l = lh >> 1, h = lh & 1;
    int sec = cb >> 1;
    int col0 = (cb & 1) * 128;
    int row0 = rb * 128;
    const float* mh = msg_w + (size_t)(l*3 + h) * 512 * HD;
    const float* m2 = msg_w + (size_t)(l*3 + 2) * 512 * HD;
    const float* U1 = upd_w + (size_t)l * 512 * HD;
    const float* U2 = U1 + (size_t)HD * HD;
    const float* P1; const float* P2; float w1, w2, scale; int addU1;
    if (sec == 0)      { P1 = mh + HD*HD; w1 = 2.f; P2 = m2 + HD*HD; w2 = 1.f; scale = 1.f/3.f; addU1 = 1; }
    else if (sec == 1) { P1 = mh;          w1 = 1.f; P2 = 0;          w2 = 0.f; scale = 1.f/3.f; addU1 = 0; }
    else if (sec == 2) { P1 = m2;          w1 = 1.f; P2 = 0;          w2 = 0.f; scale = 1.f/3.f; addU1 = 0; }
    else               { P1 = mh + HD*HD; w1 = 1.f; P2 = m2 + HD*HD; w2 = 1.f; scale = 0.5f;    addU1 = 1; }

    __shared__ float As[2][16][132];
    __shared__ float Bs[2][16][128];
    int tid = threadIdx.x;
    int tx = tid & 15, ty = tid >> 4;
    int ar = tid >> 2, ak = (tid & 3) * 4;
    int bk = tid >> 5, bn = (tid & 31) * 4;

    float acc[8][8];
    #pragma unroll
    for (int i = 0; i < 8; i++)
        #pragma unroll
        for (int j = 0; j < 8; j++) acc[i][j] = 0.f;

    float4 a0v, a1v, b0v, b1v;
    {
        int r0 = row0 + ar, r1 = row0 + ar + 64;
        a0v = ld4(&P1[(size_t)r0*HD + ak]);
        a1v = ld4(&P1[(size_t)r1*HD + ak]);
        if (P2) { a0v = f4fma(w2/w1, ld4(&P2[(size_t)r0*HD + ak]), a0v);
                  a1v = f4fma(w2/w1, ld4(&P2[(size_t)r1*HD + ak]), a1v); }
        b0v = ld4(&U2[(size_t)bk*HD + col0 + bn]);
        b1v = ld4(&U2[(size_t)(bk+8)*HD + col0 + bn]);
    }
    As[0][ak+0][ar]=a0v.x; As[0][ak+1][ar]=a0v.y; As[0][ak+2][ar]=a0v.z; As[0][ak+3][ar]=a0v.w;
    As[0][ak+0][64+ar]=a1v.x; As[0][ak+1][64+ar]=a1v.y; As[0][ak+2][64+ar]=a1v.z; As[0][ak+3][64+ar]=a1v.w;
    *(float4*)&Bs[0][bk][bn] = b0v; *(float4*)&Bs[0][bk+8][bn] = b1v;
    __syncthreads();

    int buf = 0;
    #pragma unroll 1
    for (int t = 0; t < 16; t++) {
        if (t < 15) {
            int k0 = (t + 1) * 16;
            int r0 = row0 + ar, r1 = row0 + ar + 64;
            a0v = ld4(&P1[(size_t)r0*HD + k0 + ak]);
            a1v = ld4(&P1[(size_t)r1*HD + k0 + ak]);
            if (P2) { a0v = f4fma(w2/w1, ld4(&P2[(size_t)r0*HD + k0 + ak]), a0v);
                      a1v = f4fma(w2/w1, ld4(&P2[(size_t)r1*HD + k0 + ak]), a1v); }
            b0v = ld4(&U2[(size_t)(k0+bk)*HD + col0 + bn]);
            b1v = ld4(&U2[(size_t)(k0+bk+8)*HD + col0 + bn]);
        }
        #pragma unroll
        for (int k = 0; k < 16; k++) {
            float4 pa0 = *(float4*)&As[buf][k][ty*4];
            float4 pa1 = *(float4*)&As[buf][k][64 + ty*4];
            float4 pb0 = *(float4*)&Bs[buf][k][tx*4];
            float4 pb1 = *(float4*)&Bs[buf][k][64 + tx*4];
            float aa[8] = {pa0.x,pa0.y,pa0.z,pa0.w,pa1.x,pa1.y,pa1.z,pa1.w};
            float bb[8] = {pb0.x,pb0.y,pb0.z,pb0.w,pb1.x,pb1.y,pb1.z,pb1.w};
            #pragma unroll
            for (int i = 0; i < 8; i++)
                #pragma unroll
                for (int j = 0; j < 8; j++)
                    acc[i][j] = fmaf(aa[i], bb[j], acc[i][j]);
        }
        if (t < 15) {
            int nb2 = buf ^ 1;
            As[nb2][ak+0][ar]=a0v.x; As[nb2][ak+1][ar]=a0v.y; As[nb2][ak+2][ar]=a0v.z; As[nb2][ak+3][ar]=a0v.w;
            As[nb2][ak+0][64+ar]=a1v.x; As[nb2][ak+1][64+ar]=a1v.y; As[nb2][ak+2][64+ar]=a1v.z; As[nb2][ak+3][64+ar]=a1v.w;
            *(float4*)&Bs[nb2][bk][bn] = b0v; *(float4*)&Bs[nb2][bk+8][bn] = b1v;
        }
        __syncthreads();
        buf ^= 1;
    }

    float sc = w1 * scale;
    #pragma unroll
    for (int ih = 0; ih < 2; ih++)
        #pragma unroll
        for (int ii = 0; ii < 4; ii++) {
            int r = row0 + ih*64 + ty*4 + ii;          // k index
            #pragma unroll
            for (int jh = 0; jh < 2; jh++) {
                int c = col0 + jh*64 + tx*4;           // n index (within 256)
                float vv[4];
                #pragma unroll
                for (int j = 0; j < 4; j++) vv[j] = acc[ih*4+ii][jh*4+j] * sc;
                if (addU1) {
                    float4 u = ld4(&U1[(size_t)r*HD + c]);
                    vv[0]+=u.x; vv[1]+=u.y; vv[2]+=u.z; vv[3]+=u.w;
                }
                if (sec < 3) {
                    #pragma unroll
                    for (int j = 0; j < 4; j++) {
                        int n = sec*HD + c + j;
                        size_t o = ((size_t)lh*NWC + n)*HD + r;
                        __nv_bfloat16 hi = __float2bfloat16(vv[j]);
                        g_wth[o] = hi;
                        g_wtl[o] = __float2bfloat16(vv[j] - __bfloat162float(hi));
                    }
                } else {
                    float4 v = make_float4(vv[0],vv[1],vv[2],vv[3]);
                    *(float4*)&g_We[(size_t)lh*HD*HD + (size_t)r*HD + c] = v;
                }
            }
        }
}

// ---------------- bias folding ----------------
__global__ void bias_kernel(const float* __restrict__ msg_b,
                            const float* __restrict__ upd_w,
                            const float* __restrict__ upd_b) {
    int lh = blockIdx.x; int l = lh >> 1, h = lh & 1;
    int c = threadIdx.x;
    __shared__ float v1[HD], v2[HD];
    float mbh = msg_b[(l*3 + h)*HD + c];
    float mb2 = msg_b[(l*3 + 2)*HD + c];
    v1[c] = 2.f*mbh + mb2;
    v2[c] = mbh + mb2;
    __syncthreads();
    const float* U2 = upd_w + ((size_t)l*512 + HD) * HD;
    float s1 = 0.f, s2 = 0.f;
    for (int k = 0; k < HD; k++) {
        float u = U2[(size_t)k*HD + c];
        s1 += v1[k]*u; s2 += v2[k]*u;
    }
    g_bias [lh*HD + c] = s1*(1.f/3.f) + upd_b[l*HD + c];
    g_bias2[lh*HD + c] = s2*0.5f     + upd_b[l*HD + c];
}

// ---------------- tensor-core GEMM via mma.sync: T = X @ Wt^T ------------
// C[128x128] per CTA; BK=32; 3-stage cp.async; split-bf16 (3 products).
// SMEM rows padded to 80B: 8 row-groups start at banks {0,20,8,28,16,4,24,12}
// -> conflict-free 32-bit fragment loads.
#define STG_A 10240              // 128 rows * 80B per stage per matrix
#define OFF_AL (3*STG_A)
#define OFF_BH (6*STG_A)
#define OFF_BL (9*STG_A)
#define SMEM_MMA (12*STG_A)      // 122880 B

__global__ __launch_bounds__(256, 1) void gemm_mma(int l) {
    extern __shared__ __align__(16) char sm[];
    uint32_t sb = smem_u32(sm);
    int tid = threadIdx.x, wid = tid >> 5, lane = tid & 31;
    int cb = blockIdx.x, rb = blockIdx.y, half = blockIdx.z;
    int lh = l*2 + half;
    const __nv_bfloat16* Axh = g_xh + (size_t)half*NB*HD;
    const __nv_bfloat16* Axl = g_xl + (size_t)half*NB*HD;
    const __nv_bfloat16* Bwh = g_wth + (size_t)lh*NWC*HD;
    const __nv_bfloat16* Bwl = g_wtl + (size_t)lh*NWC*HD;

    // per-thread load coords (2 x 16B per matrix per stage)
    int lr0 = tid >> 2, lseg = tid & 3;          // idx = tid, tid+256
    int an0 = rb*128 + lr0;      if (an0 >= NB) an0 = NB-1;
    int an1 = rb*128 + lr0 + 64; if (an1 >= NB) an1 = NB-1;
    int bn0 = cb*128 + lr0, bn1 = cb*128 + lr0 + 64;

    #define LOAD_STAGE(s, k0) do {                                             \
        uint32_t d0 = sb + (uint32_t)(s)*STG_A + lr0*80 + lseg*16;             \
        uint32_t d1 = d0 + 64*80;                                              \
        size_t ka = (size_t)(k0) + lseg*8;                                     \
        cpa16(d0,          Axh + (size_t)an0*HD + ka);                         \
        cpa16(d1,          Axh + (size_t)an1*HD + ka);                         \
        cpa16(d0 + OFF_AL, Axl + (size_t)an0*HD + ka);                         \
        cpa16(d1 + OFF_AL, Axl + (size_t)an1*HD + ka);                         \
        cpa16(d0 + OFF_BH, Bwh + (size_t)bn0*HD + ka);                         \
        cpa16(d1 + OFF_BH, Bwh + (size_t)bn1*HD + ka);                         \
        cpa16(d0 + OFF_BL, Bwl + (size_t)bn0*HD + ka);                         \
        cpa16(d1 + OFF_BL, Bwl + (size_t)bn1*HD + ka);                         \
        asm volatile("cp.async.commit_group;" ::: "memory");                   \
    } while (0)

    float acc[4][4][4];
    #pragma unroll
    for (int i = 0; i < 4; i++)
        #pragma unroll
        for (int j = 0; j < 4; j++)
            #pragma unroll
            for (int q = 0; q < 4; q++) acc[i][j][q] = 0.f;

    LOAD_STAGE(0, 0);
    LOAD_STAGE(1, 32);

    int g = lane >> 2, tb = (lane & 3) * 4;
    int warp_m = (wid >> 2) * 64, warp_n = (wid & 3) * 32;

    #pragma unroll 1
    for (int kt = 0; kt < 8; kt++) {
        if (kt < 7) asm volatile("cp.async.wait_group 1;" ::: "memory");
        else        asm volatile("cp.async.wait_group 0;" ::: "memory");
        __syncthreads();
        if (kt + 2 < 8) { int s2 = (kt + 2) % 3; LOAD_STAGE(s2, (kt + 2) * 32); }
        int s = kt % 3;
        const char* aH = sm + (size_t)s*STG_A;
        const char* aL = aH + OFF_AL;
        const char* bH = aH + OFF_BH;
        const char* bL = aH + OFF_BL;
        #pragma unroll
        for (int k16 = 0; k16 < 2; k16++) {
            int ko = k16*32 + tb;
            uint32_t ah[4][4], al[4][4], bh[4][2], bl[4][2];
            #pragma unroll
            for (int i = 0; i < 4; i++) {
                const char* p = aH + (warp_m + i*16 + g)*80 + ko;
                ah[i][0] = *(const uint32_t*)p;
                ah[i][1] = *(const uint32_t*)(p + 640);
                ah[i][2] = *(const uint32_t*)(p + 16);
                ah[i][3] = *(const uint32_t*)(p + 656);
                const char* q = aL + (warp_m + i*16 + g)*80 + ko;
                al[i][0] = *(const uint32_t*)q;
                al[i][1] = *(const uint32_t*)(q + 640);
                al[i][2] = *(const uint32_t*)(q + 16);
                al[i][3] = *(const uint32_t*)(q + 656);
            }
            #pragma unroll
            for (int j = 0; j < 4; j++) {
                const char* p = bH + (warp_n + j*8 + g)*80 + ko;
                bh[j][0] = *(const uint32_t*)p;
                bh[j][1] = *(const uint32_t*)(p + 16);
                const char* q = bL + (warp_n + j*8 + g)*80 + ko;
                bl[j][0] = *(const uint32_t*)q;
                bl[j][1] = *(const uint32_t*)(q + 16);
            }
            #pragma unroll
            for (int i = 0; i < 4; i++)
                #pragma unroll
                for (int j = 0; j < 4; j++) {
                    MMA3(acc[i][j], ah[i], bh[j]);
                    MMA3(acc[i][j], ah[i], bl[j]);
                    MMA3(acc[i][j], al[i], bh[j]);
                }
        }
    }

    // epilogue: stage C through SMEM, coalesced store
    __syncthreads();
    float* Cs = (float*)sm;                    // 128 x 132
    int ct = (lane & 3) * 2;
    #pragma unroll
    for (int i = 0; i < 4; i++)
        #pragma unroll
        for (int j = 0; j < 4; j++) {
            int r = warp_m + i*16 + g;
            int c = warp_n + j*8 + ct;
            *(float2*)&Cs[(size_t)r*132 + c]      = make_float2(acc[i][j][0], acc[i][j][1]);
            *(float2*)&Cs[(size_t)(r+8)*132 + c]  = make_float2(acc[i][j][2], acc[i][j][3]);
        }
    __syncthreads();
    #pragma unroll
    for (int it = 0; it < 16; it++) {
        int idx = tid + it*256;
        int r = idx >> 5, c4 = (idx & 31) * 4;
        int node = rb*128 + r;
        if (node < NB)
            *(float4*)&g_T[((size_t)(half*NB + node))*NWC + cb*128 + c4] = *(float4*)&Cs[(size_t)r*132 + c4];
    }
    #undef LOAD_STAGE
}

// ---------------- combine: u-sum + LN + GeLU + residual + bf16 split ------
__global__ __launch_bounds__(256) void combine(int l,
        const float* __restrict__ ln_g, const float* __restrict__ ln_b) {
    int node = blockIdx.x * 8 + (threadIdx.x >> 5);
    int lane = threadIdx.x & 31;
    int half = node >= NB ? 1 : 0;
    int i = node - half * NB;
    int p = half ? node - NB : node + NB;
    int c0 = lane * 4, c1 = 128 + lane * 4;
    float4 u0, u1;

    if (i > 0 && i < NB - 1) {
        const float* tS  = g_T + (size_t)node * NWC;
        const float* tNm = g_T + (size_t)(node - 1) * NWC + 256;
        const float* tNp = g_T + (size_t)(node + 1) * NWC + 256;
        const float* tX  = g_T + (size_t)p * NWC + 512;
        const float* bi  = g_bias + (l*2 + half) * HD;
        u0 = f4add(f4add(ld4(tS+c0), ld4(tNm+c0)), f4add(ld4(tNp+c0), f4add(ld4(tX+c0), ld4(bi+c0))));
        u1 = f4add(f4add(ld4(tS+c1), ld4(tNm+c1)), f4add(ld4(tNp+c1), f4add(ld4(tX+c1), ld4(bi+c1))));
    } else {
        int nn = (i == 0) ? node + 1 : node - 1;
        const float* E  = g_We + (size_t)(l*2 + half) * HD * HD;
        const float* xg = g_h + (size_t)node * HD;
        float4 s0 = f4z(), s1 = f4z();
        #pragma unroll 4
        for (int k = 0; k < HD; k++) {
            float xv = xg[k];
            s0 = f4fma(xv, ld4(&E[(size_t)k*HD + c0]), s0);
            s1 = f4fma(xv, ld4(&E[(size_t)k*HD + c1]), s1);
        }
        const float* tN  = g_T + (size_t)nn * NWC + 256;
        const float* tX  = g_T + (size_t)p * NWC + 512;
        const float* bi2 = g_bias2 + (l*2 + half) * HD;
        u0 = f4add(s0, f4fma(1.5f, f4add(ld4(tN+c0), ld4(tX+c0)), ld4(bi2+c0)));
        u1 = f4add(s1, f4fma(1.5f, f4add(ld4(tN+c1), ld4(tX+c1)), ld4(bi2+c1)));
    }

    float s = u0.x+u0.y+u0.z+u0.w + u1.x+u1.y+u1.z+u1.w;
    float q = u0.x*u0.x+u0.y*u0.y+u0.z*u0.z+u0.w*u0.w
            + u1.x*u1.x+u1.y*u1.y+u1.z*u1.z+u1.w*u1.w;
    #pragma unroll
    for (int off = 16; off; off >>= 1) {
        s += __shfl_xor_sync(0xffffffff, s, off);
        q += __shfl_xor_sync(0xffffffff, q, off);
    }
    float mu = s * (1.f/HD);
    float rs = rsqrtf(q * (1.f/HD) - mu*mu + 1e-5f);

    const float* lg = ln_g + l*HD;
    const float* lb = ln_b + l*HD;
    float4 g0 = ld4(lg+c0), g1 = ld4(lg+c1);
    float4 b0 = ld4(lb+c0), b1 = ld4(lb+c1);
    size_t ho = (size_t)node * HD;
    float4 h0 = ld4(&g_h[ho+c0]), h1 = ld4(&g_h[ho+c1]);
    h0.x += gelu_exact((u0.x-mu)*rs*g0.x + b0.x);
    h0.y += gelu_exact((u0.y-mu)*rs*g0.y + b0.y);
    h0.z += gelu_exact((u0.z-mu)*rs*g0.z + b0.z);
    h0.w += gelu_exact((u0.w-mu)*rs*g0.w + b0.w);
    h1.x += gelu_exact((u1.x-mu)*rs*g1.x + b1.x);
    h1.y += gelu_exact((u1.y-mu)*rs*g1.y + b1.y);
    h1.z += gelu_exact((u1.z-mu)*rs*g1.z + b1.z);
    h1.w += gelu_exact((u1.w-mu)*rs*g1.w + b1.w);
    *(float4*)&g_h[ho+c0] = h0;
    *(float4*)&g_h[ho+c1] = h1;
    st_split(ho+c0, h0);
    st_split(ho+c1, h1);
}

// ---------------- readout ----------------
__global__ void zero_hm() { if (threadIdx.x < HD) g_hm[threadIdx.x] = 0.f; }

__global__ void colmean() {
    int c = threadIdx.x;
    int r0 = blockIdx.x * 200;
    float s = 0.f;
    for (int r = r0; r < r0 + 200; r++) s += g_h[(size_t)r * HD + c];
    atomicAdd(&g_hm[c], s);
}

__global__ void decoder(const float* __restrict__ dec1_w, const float* __restrict__ dec1_b,
                        const float* __restrict__ dec2_w, const float* __restrict__ dec2_b,
                        const float* __restrict__ Kp, const float* __restrict__ tau,
                        const float* __restrict__ tau_max, const float* __restrict__ lam,
                        float* __restrict__ out) {
    __shared__ float hm[HD], z[HD], red[64];
    int t = threadIdx.x;
    hm[t] = g_hm[t] * (1.0f / NB);
    __syncthreads();
    float acc = dec1_b[t];
    for (int k = 0; k < HD; k++) acc += hm[k] * dec1_w[k * HD + t];
    z[t] = gelu_exact(acc);
    __syncthreads();
    if (t < 128) {
        float a = dec2_b[t];
        for (int k = 0; k < HD; k++) a += z[k] * dec2_w[k * 128 + t];
        out[t] = a;
    }
    if (t < 64) {
        red[t] = Kp[t] * tau[t] / tau_max[t];
        out[129 + t] = Kp[t];
    }
    __syncthreads();
    if (t == 0) {
        float s = 0.f;
        for (int i = 0; i < 64; i++) s += red[i];
        out[128] = fabsf(lam[0]) - s;
    }
}

// ---------------- launch ----------------
extern "C" void kernel_launch(void* const* d_in, const int* in_sizes, int n_in,
                              void* d_out, int out_size) {
    const float* energy_x     = (const float*)d_in[0];
    const float* comm_x       = (const float*)d_in[1];
    const float* tau          = (const float*)d_in[2];
    const float* tau_max      = (const float*)d_in[3];
    const float* lambda_min_0 = (const float*)d_in[4];
    const float* We_w         = (const float*)d_in[5];
    const float* We_b         = (const float*)d_in[6];
    const float* Wc_w         = (const float*)d_in[7];
    const float* Wc_b         = (const float*)d_in[8];
    const float* msg_w        = (const float*)d_in[9];
    const float* msg_b        = (const float*)d_in[10];
    const float* upd_w        = (const float*)d_in[11];
    const float* upd_b        = (const float*)d_in[12];
    const float* ln_g         = (const float*)d_in[13];
    const float* ln_b         = (const float*)d_in[14];
    const float* dec1_w       = (const float*)d_in[15];
    const float* dec1_b       = (const float*)d_in[16];
    const float* dec2_w       = (const float*)d_in[17];
    const float* dec2_b       = (const float*)d_in[18];
    const float* K_param      = (const float*)d_in[19];
    float* out = (float*)d_out;

    cudaFuncSetAttribute(gemm_mma, cudaFuncAttributeMaxDynamicSharedMemorySize, SMEM_MMA);

    gemm_pre<<<dim3(8, 2, 8), 256>>>(msg_w, upd_w);
    bias_kernel<<<8, 256>>>(msg_b, upd_w, upd_b);
    encode<<<(TWO_N * HD / 4 + 255) / 256, 256>>>(energy_x, comm_x, We_w, We_b, Wc_w, Wc_b);

    for (int l = 0; l < NL; l++) {
        gemm_mma<<<dim3(6, (NB + 127) / 128, 2), 256, SMEM_MMA>>>(l);
        combine<<<TWO_N / 8, 256>>>(l, ln_g, ln_b);
    }

    zero_hm<<<1, 256>>>();
    colmean<<<100, 256>>>();
    decoder<<<1, 256>>>(dec1_w, dec1_b, dec2_w, dec2_b,
                        K_param, tau, tau_max, lambda_min_0, out);
}

// round 5
// speedup vs baseline: 4.6743x; 1.1263x over previous
#include <cuda_runtime.h>
#include <cuda_bf16.h>
#include <math.h>
#include <stdint.h>

#define NB 20000
#define HD 256
#define NL 4
#define TWO_N (2*NB)
#define NWC 768

// ---------------- device scratch ----------------
__device__ float g_h  [(size_t)TWO_N * HD];
__device__ __nv_bfloat16 g_xh[(size_t)TWO_N * HD];
__device__ __nv_bfloat16 g_xl[(size_t)TWO_N * HD];
__device__ float g_T  [(size_t)TWO_N * NWC];
__device__ __nv_bfloat16 g_wth[(size_t)NL * 2 * NWC * HD];  // [lh][n][k]
__device__ __nv_bfloat16 g_wtl[(size_t)NL * 2 * NWC * HD];
__device__ float g_We [(size_t)NL * 2 * HD * HD];
__device__ float g_bias [NL * 2 * HD];
__device__ float g_bias2[NL * 2 * HD];
__device__ float g_hm [HD];

// ---------------- helpers ----------------
__device__ __forceinline__ float gelu_exact(float x) {
    return 0.5f * x * (1.0f + erff(x * 0.70710678118654752f));
}
__device__ __forceinline__ float4 ld4(const float* p) { return *(const float4*)p; }
__device__ __forceinline__ float4 f4z() { return make_float4(0.f,0.f,0.f,0.f); }
__device__ __forceinline__ float4 f4add(float4 a, float4 b) {
    return make_float4(a.x+b.x, a.y+b.y, a.z+b.z, a.w+b.w);
}
__device__ __forceinline__ float4 f4fma(float s, float4 a, float4 b) {
    return make_float4(fmaf(s,a.x,b.x), fmaf(s,a.y,b.y), fmaf(s,a.z,b.z), fmaf(s,a.w,b.w));
}
__device__ __forceinline__ uint32_t smem_u32(const void* p) {
    uint32_t a;
    asm("{ .reg .u64 t; cvta.to.shared.u64 t, %1; cvt.u32.u64 %0, t; }" : "=r"(a) : "l"(p));
    return a;
}
__device__ __forceinline__ void cpa16(uint32_t s, const void* g) {
    asm volatile("cp.async.cg.shared.global [%0], [%1], 16;" :: "r"(s), "l"(g));
}
__device__ __forceinline__ void st_split(size_t off, float4 v) {
    __nv_bfloat16 hx = __float2bfloat16(v.x), hy = __float2bfloat16(v.y);
    __nv_bfloat16 hz = __float2bfloat16(v.z), hw = __float2bfloat16(v.w);
    __nv_bfloat162* ph = (__nv_bfloat162*)&g_xh[off];
    ph[0] = __nv_bfloat162(hx, hy); ph[1] = __nv_bfloat162(hz, hw);
    __nv_bfloat162* pl = (__nv_bfloat162*)&g_xl[off];
    pl[0] = __nv_bfloat162(__float2bfloat16(v.x - __bfloat162float(hx)),
                           __float2bfloat16(v.y - __bfloat162float(hy)));
    pl[1] = __nv_bfloat162(__float2bfloat16(v.z - __bfloat162float(hz)),
                           __float2bfloat16(v.w - __bfloat162float(hw)));
}

#define MMA2(c, A, b0v, b1v) asm volatile( \
    "mma.sync.aligned.m16n8k16.row.col.f32.bf16.bf16.f32 " \
    "{%0,%1,%2,%3},{%4,%5,%6,%7},{%8,%9},{%0,%1,%2,%3};" \
    : "+f"(c[0]),"+f"(c[1]),"+f"(c[2]),"+f"(c[3]) \
    : "r"(A[0]),"r"(A[1]),"r"(A[2]),"r"(A[3]),"r"(b0v),"r"(b1v))

#define LDM4(r, addr) asm volatile( \
    "ldmatrix.sync.aligned.m8n8.x4.shared.b16 {%0,%1,%2,%3}, [%4];" \
    : "=r"((r)[0]),"=r"((r)[1]),"=r"((r)[2]),"=r"((r)[3]) : "r"(addr))

// ---------------- encoders ----------------
__global__ void encode(const float* __restrict__ ex, const float* __restrict__ cx,
                       const float* __restrict__ Wew, const float* __restrict__ Web,
                       const float* __restrict__ Wcw, const float* __restrict__ Wcb) {
    int idx = blockIdx.x * blockDim.x + threadIdx.x;
    if (idx >= TWO_N * HD / 4) return;
    int c = (idx & 63) * 4;
    int g = idx >> 6;
    float4 v;
    if (g < NB) {
        const float* x = ex + (size_t)g * 5;
        v = ld4(&Web[c]);
        #pragma unroll
        for (int j = 0; j < 5; j++) v = f4fma(x[j], ld4(&Wew[j * HD + c]), v);
    } else {
        const float* x = cx + (size_t)(g - NB) * 3;
        v = ld4(&Wcb[c]);
        #pragma unroll
        for (int j = 0; j < 3; j++) v = f4fma(x[j], ld4(&Wcw[j * HD + c]), v);
    }
    size_t off = (size_t)g * HD + c;
    *(float4*)&g_h[off] = v;
    st_split(off, v);
}

// ---------------- weight folding ----------------
__global__ __launch_bounds__(256, 2) void gemm_pre(const float* __restrict__ msg_w,
                                                   const float* __restrict__ upd_w) {
    int cb = blockIdx.x, rb = blockIdx.y, lh = blockIdx.z;
    int l = lh >> 1, h = lh & 1;
    int sec = cb >> 1;
    int col0 = (cb & 1) * 128;
    int row0 = rb * 128;
    const float* mh = msg_w + (size_t)(l*3 + h) * 512 * HD;
    const float* m2 = msg_w + (size_t)(l*3 + 2) * 512 * HD;
    const float* U1 = upd_w + (size_t)l * 512 * HD;
    const float* U2 = U1 + (size_t)HD * HD;
    const float* P1; const float* P2; float w1, w2, scale; int addU1;
    if (sec == 0)      { P1 = mh + HD*HD; w1 = 2.f; P2 = m2 + HD*HD; w2 = 1.f; scale = 1.f/3.f; addU1 = 1; }
    else if (sec == 1) { P1 = mh;          w1 = 1.f; P2 = 0;          w2 = 0.f; scale = 1.f/3.f; addU1 = 0; }
    else if (sec == 2) { P1 = m2;          w1 = 1.f; P2 = 0;          w2 = 0.f; scale = 1.f/3.f; addU1 = 0; }
    else               { P1 = mh + HD*HD; w1 = 1.f; P2 = m2 + HD*HD; w2 = 1.f; scale = 0.5f;    addU1 = 1; }

    __shared__ float As[2][16][132];
    __shared__ float Bs[2][16][128];
    int tid = threadIdx.x;
    int tx = tid & 15, ty = tid >> 4;
    int ar = tid >> 2, ak = (tid & 3) * 4;
    int bk = tid >> 5, bn = (tid & 31) * 4;

    float acc[8][8];
    #pragma unroll
    for (int i = 0; i < 8; i++)
        #pragma unroll
        for (int j = 0; j < 8; j++) acc[i][j] = 0.f;

    float4 a0v, a1v, b0v, b1v;
    {
        int r0 = row0 + ar, r1 = row0 + ar + 64;
        a0v = ld4(&P1[(size_t)r0*HD + ak]);
        a1v = ld4(&P1[(size_t)r1*HD + ak]);
        if (P2) { a0v = f4fma(w2/w1, ld4(&P2[(size_t)r0*HD + ak]), a0v);
                  a1v = f4fma(w2/w1, ld4(&P2[(size_t)r1*HD + ak]), a1v); }
        b0v = ld4(&U2[(size_t)bk*HD + col0 + bn]);
        b1v = ld4(&U2[(size_t)(bk+8)*HD + col0 + bn]);
    }
    As[0][ak+0][ar]=a0v.x; As[0][ak+1][ar]=a0v.y; As[0][ak+2][ar]=a0v.z; As[0][ak+3][ar]=a0v.w;
    As[0][ak+0][64+ar]=a1v.x; As[0][ak+1][64+ar]=a1v.y; As[0][ak+2][64+ar]=a1v.z; As[0][ak+3][64+ar]=a1v.w;
    *(float4*)&Bs[0][bk][bn] = b0v; *(float4*)&Bs[0][bk+8][bn] = b1v;
    __syncthreads();

    int buf = 0;
    #pragma unroll 1
    for (int t = 0; t < 16; t++) {
        if (t < 15) {
            int k0 = (t + 1) * 16;
            int r0 = row0 + ar, r1 = row0 + ar + 64;
            a0v = ld4(&P1[(size_t)r0*HD + k0 + ak]);
            a1v = ld4(&P1[(size_t)r1*HD + k0 + ak]);
            if (P2) { a0v = f4fma(w2/w1, ld4(&P2[(size_t)r0*HD + k0 + ak]), a0v);
                      a1v = f4fma(w2/w1, ld4(&P2[(size_t)r1*HD + k0 + ak]), a1v); }
            b0v = ld4(&U2[(size_t)(k0+bk)*HD + col0 + bn]);
            b1v = ld4(&U2[(size_t)(k0+bk+8)*HD + col0 + bn]);
        }
        #pragma unroll
        for (int k = 0; k < 16; k++) {
            float4 pa0 = *(float4*)&As[buf][k][ty*4];
            float4 pa1 = *(float4*)&As[buf][k][64 + ty*4];
            float4 pb0 = *(float4*)&Bs[buf][k][tx*4];
            float4 pb1 = *(float4*)&Bs[buf][k][64 + tx*4];
            float aa[8] = {pa0.x,pa0.y,pa0.z,pa0.w,pa1.x,pa1.y,pa1.z,pa1.w};
            float bb[8] = {pb0.x,pb0.y,pb0.z,pb0.w,pb1.x,pb1.y,pb1.z,pb1.w};
            #pragma unroll
            for (int i = 0; i < 8; i++)
                #pragma unroll
                for (int j = 0; j < 8; j++)
                    acc[i][j] = fmaf(aa[i], bb[j], acc[i][j]);
        }
        if (t < 15) {
            int nb2 = buf ^ 1;
            As[nb2][ak+0][ar]=a0v.x; As[nb2][ak+1][ar]=a0v.y; As[nb2][ak+2][ar]=a0v.z; As[nb2][ak+3][ar]=a0v.w;
            As[nb2][ak+0][64+ar]=a1v.x; As[nb2][ak+1][64+ar]=a1v.y; As[nb2][ak+2][64+ar]=a1v.z; As[nb2][ak+3][64+ar]=a1v.w;
            *(float4*)&Bs[nb2][bk][bn] = b0v; *(float4*)&Bs[nb2][bk+8][bn] = b1v;
        }
        __syncthreads();
        buf ^= 1;
    }

    float sc = w1 * scale;
    #pragma unroll
    for (int ih = 0; ih < 2; ih++)
        #pragma unroll
        for (int ii = 0; ii < 4; ii++) {
            int r = row0 + ih*64 + ty*4 + ii;          // k index
            #pragma unroll
            for (int jh = 0; jh < 2; jh++) {
                int c = col0 + jh*64 + tx*4;           // n index (within 256)
                float vv[4];
                #pragma unroll
                for (int j = 0; j < 4; j++) vv[j] = acc[ih*4+ii][jh*4+j] * sc;
                if (addU1) {
                    float4 u = ld4(&U1[(size_t)r*HD + c]);
                    vv[0]+=u.x; vv[1]+=u.y; vv[2]+=u.z; vv[3]+=u.w;
                }
                if (sec < 3) {
                    #pragma unroll
                    for (int j = 0; j < 4; j++) {
                        int n = sec*HD + c + j;
                        size_t o = ((size_t)lh*NWC + n)*HD + r;
                        __nv_bfloat16 hi = __float2bfloat16(vv[j]);
                        g_wth[o] = hi;
                        g_wtl[o] = __float2bfloat16(vv[j] - __bfloat162float(hi));
                    }
                } else {
                    float4 v = make_float4(vv[0],vv[1],vv[2],vv[3]);
                    *(float4*)&g_We[(size_t)lh*HD*HD + (size_t)r*HD + c] = v;
                }
            }
        }
}

// ---------------- bias folding ----------------
__global__ void bias_kernel(const float* __restrict__ msg_b,
                            const float* __restrict__ upd_w,
                            const float* __restrict__ upd_b) {
    int lh = blockIdx.x; int l = lh >> 1, h = lh & 1;
    int c = threadIdx.x;
    __shared__ float v1[HD], v2[HD];
    float mbh = msg_b[(l*3 + h)*HD + c];
    float mb2 = msg_b[(l*3 + 2)*HD + c];
    v1[c] = 2.f*mbh + mb2;
    v2[c] = mbh + mb2;
    __syncthreads();
    const float* U2 = upd_w + ((size_t)l*512 + HD) * HD;
    float s1 = 0.f, s2 = 0.f;
    for (int k = 0; k < HD; k++) {
        float u = U2[(size_t)k*HD + c];
        s1 += v1[k]*u; s2 += v2[k]*u;
    }
    g_bias [lh*HD + c] = s1*(1.f/3.f) + upd_b[l*HD + c];
    g_bias2[lh*HD + c] = s2*0.5f     + upd_b[l*HD + c];
}

// ---------------- tensor-core GEMM via mma.sync + ldmatrix ---------------
// C[128x128]/CTA; BK=32; 2-stage cp.async; 2 CTAs/SM; split-bf16 (3 products).
// SMEM rows 80B: conflict-free for both cp.async stores and ldmatrix reads.
#define MAT_SZ  10240            // 128 rows * 80 B
#define STG_TOT 40960            // AH | AL | BH | BL
#define SMEM_MMA 81920           // 2 stages

__global__ __launch_bounds__(256, 2) void gemm_mma(int l) {
    extern __shared__ __align__(16) char sm[];
    uint32_t sb = smem_u32(sm);
    int tid = threadIdx.x, wid = tid >> 5, lane = tid & 31;
    int cb = blockIdx.x, rb = blockIdx.y, half = blockIdx.z;
    int lh = l*2 + half;
    const __nv_bfloat16* Axh = g_xh + (size_t)half*NB*HD;
    const __nv_bfloat16* Axl = g_xl + (size_t)half*NB*HD;
    const __nv_bfloat16* Bwh = g_wth + (size_t)lh*NWC*HD;
    const __nv_bfloat16* Bwl = g_wtl + (size_t)lh*NWC*HD;

    // loader coords: thread -> (row lr0 / lr0+64, 16B segment lseg)
    int lr0 = tid >> 2, lseg = tid & 3;
    int an0 = rb*128 + lr0;      if (an0 >= NB) an0 = NB-1;
    int an1 = rb*128 + lr0 + 64; if (an1 >= NB) an1 = NB-1;
    int bn0 = cb*128 + lr0, bn1 = cb*128 + lr0 + 64;

    #define LOAD_STAGE(s, k0) do {                                             \
        uint32_t d0 = sb + (uint32_t)(s)*STG_TOT + lr0*80 + lseg*16;           \
        uint32_t d1 = d0 + 64*80;                                              \
        size_t ka = (size_t)(k0) + lseg*8;                                     \
        cpa16(d0,            Axh + (size_t)an0*HD + ka);                       \
        cpa16(d1,            Axh + (size_t)an1*HD + ka);                       \
        cpa16(d0 + MAT_SZ,   Axl + (size_t)an0*HD + ka);                       \
        cpa16(d1 + MAT_SZ,   Axl + (size_t)an1*HD + ka);                       \
        cpa16(d0 + 2*MAT_SZ, Bwh + (size_t)bn0*HD + ka);                       \
        cpa16(d1 + 2*MAT_SZ, Bwh + (size_t)bn1*HD + ka);                       \
        cpa16(d0 + 3*MAT_SZ, Bwl + (size_t)bn0*HD + ka);                       \
        cpa16(d1 + 3*MAT_SZ, Bwl + (size_t)bn1*HD + ka);                       \
        asm volatile("cp.async.commit_group;" ::: "memory");                   \
    } while (0)

    float acc[4][4][4];
    #pragma unroll
    for (int i = 0; i < 4; i++)
        #pragma unroll
        for (int j = 0; j < 4; j++)
            #pragma unroll
            for (int q = 0; q < 4; q++) acc[i][j][q] = 0.f;

    LOAD_STAGE(0, 0);
    LOAD_STAGE(1, 32);

    int warp_m = (wid >> 2) * 64, warp_n = (wid & 3) * 32;
    int la7 = lane & 7, lb8 = (lane >> 3) & 1, lhi = lane >> 4;
    // A ldmatrix.x4: mats = (m+0,k0-7)(m+8,k0-7)(m+0,k8-15)(m+8,k8-15)
    uint32_t aoff = (uint32_t)(warp_m + la7 + lb8*8)*80 + lhi*16;
    // B ldmatrix.x4: mats = (j,k0-7)(j,k8-15)(j+1,k0-7)(j+1,k8-15)
    uint32_t boff = 2*MAT_SZ + (uint32_t)(warp_n + lhi*8 + la7)*80 + lb8*16;

    #pragma unroll 1
    for (int kt = 0; kt < 8; kt++) {
        if (kt < 7) asm volatile("cp.async.wait_group 1;" ::: "memory");
        else        asm volatile("cp.async.wait_group 0;" ::: "memory");
        __syncthreads();
        uint32_t stg = sb + (uint32_t)(kt & 1) * STG_TOT;
        #pragma unroll
        for (int k16 = 0; k16 < 2; k16++) {
            uint32_t ko = k16 * 32;
            uint32_t ah[4][4], al[4][4];
            #pragma unroll
            for (int i = 0; i < 4; i++) {
                LDM4(ah[i], stg + aoff + i*1280 + ko);
                LDM4(al[i], stg + MAT_SZ + aoff + i*1280 + ko);
            }
            #pragma unroll
            for (int jj = 0; jj < 2; jj++) {
                uint32_t bh[4], bl[4];
                LDM4(bh, stg + boff + jj*1280 + ko);
                LDM4(bl, stg + MAT_SZ + boff + jj*1280 + ko);
                #pragma unroll
                for (int j2 = 0; j2 < 2; j2++) {
                    int j = jj*2 + j2;
                    #pragma unroll
                    for (int i = 0; i < 4; i++) {
                        MMA2(acc[i][j], ah[i], bh[j2*2], bh[j2*2+1]);
                        MMA2(acc[i][j], ah[i], bl[j2*2], bl[j2*2+1]);
                        MMA2(acc[i][j], al[i], bh[j2*2], bh[j2*2+1]);
                    }
                }
            }
        }
        __syncthreads();
        if (kt + 2 < 8) LOAD_STAGE(kt & 1, (kt + 2) * 32);
    }

    // epilogue: stage C through SMEM, coalesced store
    asm volatile("cp.async.wait_group 0;" ::: "memory");
    __syncthreads();
    float* Cs = (float*)sm;                    // 128 x 132 floats = 67584 B
    int g = lane >> 2;
    int ct = (lane & 3) * 2;
    #pragma unroll
    for (int i = 0; i < 4; i++)
        #pragma unroll
        for (int j = 0; j < 4; j++) {
            int r = warp_m + i*16 + g;
            int c = warp_n + j*8 + ct;
            *(float2*)&Cs[(size_t)r*132 + c]      = make_float2(acc[i][j][0], acc[i][j][1]);
            *(float2*)&Cs[(size_t)(r+8)*132 + c]  = make_float2(acc[i][j][2], acc[i][j][3]);
        }
    __syncthreads();
    #pragma unroll
    for (int it = 0; it < 16; it++) {
        int idx = tid + it*256;
        int r = idx >> 5, c4 = (idx & 31) * 4;
        int node = rb*128 + r;
        if (node < NB)
            *(float4*)&g_T[((size_t)(half*NB + node))*NWC + cb*128 + c4] = *(float4*)&Cs[(size_t)r*132 + c4];
    }
    #undef LOAD_STAGE
}

// ---------------- combine: u-sum + LN + GeLU + residual + bf16 split ------
__global__ __launch_bounds__(256) void combine(int l,
        const float* __restrict__ ln_g, const float* __restrict__ ln_b) {
    int node = blockIdx.x * 8 + (threadIdx.x >> 5);
    int lane = threadIdx.x & 31;
    int half = node >= NB ? 1 : 0;
    int i = node - half * NB;
    int p = half ? node - NB : node + NB;
    int c0 = lane * 4, c1 = 128 + lane * 4;
    float4 u0, u1;

    if (i > 0 && i < NB - 1) {
        const float* tS  = g_T + (size_t)node * NWC;
        const float* tNm = g_T + (size_t)(node - 1) * NWC + 256;
        const float* tNp = g_T + (size_t)(node + 1) * NWC + 256;
        const float* tX  = g_T + (size_t)p * NWC + 512;
        const float* bi  = g_bias + (l*2 + half) * HD;
        u0 = f4add(f4add(ld4(tS+c0), ld4(tNm+c0)), f4add(ld4(tNp+c0), f4add(ld4(tX+c0), ld4(bi+c0))));
        u1 = f4add(f4add(ld4(tS+c1), ld4(tNm+c1)), f4add(ld4(tNp+c1), f4add(ld4(tX+c1), ld4(bi+c1))));
    } else {
        int nn = (i == 0) ? node + 1 : node - 1;
        const float* E  = g_We + (size_t)(l*2 + half) * HD * HD;
        const float* xg = g_h + (size_t)node * HD;
        float4 s0 = f4z(), s1 = f4z();
        #pragma unroll 4
        for (int k = 0; k < HD; k++) {
            float xv = xg[k];
            s0 = f4fma(xv, ld4(&E[(size_t)k*HD + c0]), s0);
            s1 = f4fma(xv, ld4(&E[(size_t)k*HD + c1]), s1);
        }
        const float* tN  = g_T + (size_t)nn * NWC + 256;
        const float* tX  = g_T + (size_t)p * NWC + 512;
        const float* bi2 = g_bias2 + (l*2 + half) * HD;
        u0 = f4add(s0, f4fma(1.5f, f4add(ld4(tN+c0), ld4(tX+c0)), ld4(bi2+c0)));
        u1 = f4add(s1, f4fma(1.5f, f4add(ld4(tN+c1), ld4(tX+c1)), ld4(bi2+c1)));
    }

    float s = u0.x+u0.y+u0.z+u0.w + u1.x+u1.y+u1.z+u1.w;
    float q = u0.x*u0.x+u0.y*u0.y+u0.z*u0.z+u0.w*u0.w
            + u1.x*u1.x+u1.y*u1.y+u1.z*u1.z+u1.w*u1.w;
    #pragma unroll
    for (int off = 16; off; off >>= 1) {
        s += __shfl_xor_sync(0xffffffff, s, off);
        q += __shfl_xor_sync(0xffffffff, q, off);
    }
    float mu = s * (1.f/HD);
    float rs = rsqrtf(q * (1.f/HD) - mu*mu + 1e-5f);

    const float* lg = ln_g + l*HD;
    const float* lb = ln_b + l*HD;
    float4 g0 = ld4(lg+c0), g1 = ld4(lg+c1);
    float4 b0 = ld4(lb+c0), b1 = ld4(lb+c1);
    size_t ho = (size_t)node * HD;
    float4 h0 = ld4(&g_h[ho+c0]), h1 = ld4(&g_h[ho+c1]);
    h0.x += gelu_exact((u0.x-mu)*rs*g0.x + b0.x);
    h0.y += gelu_exact((u0.y-mu)*rs*g0.y + b0.y);
    h0.z += gelu_exact((u0.z-mu)*rs*g0.z + b0.z);
    h0.w += gelu_exact((u0.w-mu)*rs*g0.w + b0.w);
    h1.x += gelu_exact((u1.x-mu)*rs*g1.x + b1.x);
    h1.y += gelu_exact((u1.y-mu)*rs*g1.y + b1.y);
    h1.z += gelu_exact((u1.z-mu)*rs*g1.z + b1.z);
    h1.w += gelu_exact((u1.w-mu)*rs*g1.w + b1.w);
    *(float4*)&g_h[ho+c0] = h0;
    *(float4*)&g_h[ho+c1] = h1;
    st_split(ho+c0, h0);
    st_split(ho+c1, h1);
}

// ---------------- readout ----------------
__global__ void zero_hm() { if (threadIdx.x < HD) g_hm[threadIdx.x] = 0.f; }

__global__ void colmean() {
    int c = threadIdx.x;
    int r0 = blockIdx.x * 200;
    float s = 0.f;
    for (int r = r0; r < r0 + 200; r++) s += g_h[(size_t)r * HD + c];
    atomicAdd(&g_hm[c], s);
}

__global__ void decoder(const float* __restrict__ dec1_w, const float* __restrict__ dec1_b,
                        const float* __restrict__ dec2_w, const float* __restrict__ dec2_b,
                        const float* __restrict__ Kp, const float* __restrict__ tau,
                        const float* __restrict__ tau_max, const float* __restrict__ lam,
                        float* __restrict__ out) {
    __shared__ float hm[HD], z[HD], red[64];
    int t = threadIdx.x;
    hm[t] = g_hm[t] * (1.0f / NB);
    __syncthreads();
    float acc = dec1_b[t];
    for (int k = 0; k < HD; k++) acc += hm[k] * dec1_w[k * HD + t];
    z[t] = gelu_exact(acc);
    __syncthreads();
    if (t < 128) {
        float a = dec2_b[t];
        for (int k = 0; k < HD; k++) a += z[k] * dec2_w[k * 128 + t];
        out[t] = a;
    }
    if (t < 64) {
        red[t] = Kp[t] * tau[t] / tau_max[t];
        out[129 + t] = Kp[t];
    }
    __syncthreads();
    if (t == 0) {
        float s = 0.f;
        for (int i = 0; i < 64; i++) s += red[i];
        out[128] = fabsf(lam[0]) - s;
    }
}

// ---------------- launch ----------------
extern "C" void kernel_launch(void* const* d_in, const int* in_sizes, int n_in,
                              void* d_out, int out_size) {
    const float* energy_x     = (const float*)d_in[0];
    const float* comm_x       = (const float*)d_in[1];
    const float* tau          = (const float*)d_in[2];
    const float* tau_max      = (const float*)d_in[3];
    const float* lambda_min_0 = (const float*)d_in[4];
    const float* We_w         = (const float*)d_in[5];
    const float* We_b         = (const float*)d_in[6];
    const float* Wc_w         = (const float*)d_in[7];
    const float* Wc_b         = (const float*)d_in[8];
    const float* msg_w        = (const float*)d_in[9];
    const float* msg_b        = (const float*)d_in[10];
    const float* upd_w        = (const float*)d_in[11];
    const float* upd_b        = (const float*)d_in[12];
    const float* ln_g         = (const float*)d_in[13];
    const float* ln_b         = (const float*)d_in[14];
    const float* dec1_w       = (const float*)d_in[15];
    const float* dec1_b       = (const float*)d_in[16];
    const float* dec2_w       = (const float*)d_in[17];
    const float* dec2_b       = (const float*)d_in[18];
    const float* K_param      = (const float*)d_in[19];
    float* out = (float*)d_out;

    cudaFuncSetAttribute(gemm_mma, cudaFuncAttributeMaxDynamicSharedMemorySize, SMEM_MMA);

    gemm_pre<<<dim3(8, 2, 8), 256>>>(msg_w, upd_w);
    bias_kernel<<<8, 256>>>(msg_b, upd_w, upd_b);
    encode<<<(TWO_N * HD / 4 + 255) / 256, 256>>>(energy_x, comm_x, We_w, We_b, Wc_w, Wc_b);

    for (int l = 0; l < NL; l++) {
        gemm_mma<<<dim3(6, (NB + 127) / 128, 2), 256, SMEM_MMA>>>(l);
        combine<<<TWO_N / 8, 256>>>(l, ln_g, ln_b);
    }

    zero_hm<<<1, 256>>>();
    colmean<<<100, 256>>>();
    decoder<<<1, 256>>>(dec1_w, dec1_b, dec2_w, dec2_b,
                        K_param, tau, tau_max, lambda_min_0, out);
}

// round 6
// speedup vs baseline: 5.4780x; 1.1720x over previous
#include <cuda_runtime.h>
#include <cuda_bf16.h>
#include <math.h>
#include <stdint.h>

#define NB 20000
#define HD 256
#define NL 4
#define TWO_N (2*NB)
#define NWC 768

// ---------------- device scratch ----------------
__device__ float g_h  [(size_t)TWO_N * HD];
__device__ __nv_bfloat16 g_xh[(size_t)TWO_N * HD];
__device__ float g_T  [(size_t)TWO_N * NWC];
__device__ __nv_bfloat16 g_wth[(size_t)NL * 2 * NWC * HD];  // [lh][n][k]
__device__ __nv_bfloat16 g_wtl[(size_t)NL * 2 * NWC * HD];
__device__ float g_We [(size_t)NL * 2 * HD * HD];
__device__ float g_bias [NL * 2 * HD];
__device__ float g_bias2[NL * 2 * HD];
__device__ float g_hm [HD];

// ---------------- helpers ----------------
__device__ __forceinline__ float gelu_exact(float x) {
    return 0.5f * x * (1.0f + erff(x * 0.70710678118654752f));
}
__device__ __forceinline__ float4 ld4(const float* p) { return *(const float4*)p; }
__device__ __forceinline__ float4 f4z() { return make_float4(0.f,0.f,0.f,0.f); }
__device__ __forceinline__ float4 f4add(float4 a, float4 b) {
    return make_float4(a.x+b.x, a.y+b.y, a.z+b.z, a.w+b.w);
}
__device__ __forceinline__ float4 f4fma(float s, float4 a, float4 b) {
    return make_float4(fmaf(s,a.x,b.x), fmaf(s,a.y,b.y), fmaf(s,a.z,b.z), fmaf(s,a.w,b.w));
}
__device__ __forceinline__ uint32_t smem_u32(const void* p) {
    uint32_t a;
    asm("{ .reg .u64 t; cvta.to.shared.u64 t, %1; cvt.u32.u64 %0, t; }" : "=r"(a) : "l"(p));
    return a;
}
__device__ __forceinline__ void cpa16(uint32_t s, const void* g) {
    asm volatile("cp.async.cg.shared.global [%0], [%1], 16;" :: "r"(s), "l"(g));
}
__device__ __forceinline__ void st_hi(size_t off, float4 v) {
    __nv_bfloat162* ph = (__nv_bfloat162*)&g_xh[off];
    ph[0] = __nv_bfloat162(__float2bfloat16(v.x), __float2bfloat16(v.y));
    ph[1] = __nv_bfloat162(__float2bfloat16(v.z), __float2bfloat16(v.w));
}

#define MMA2(c, A, b0v, b1v) asm volatile( \
    "mma.sync.aligned.m16n8k16.row.col.f32.bf16.bf16.f32 " \
    "{%0,%1,%2,%3},{%4,%5,%6,%7},{%8,%9},{%0,%1,%2,%3};" \
    : "+f"(c[0]),"+f"(c[1]),"+f"(c[2]),"+f"(c[3]) \
    : "r"(A[0]),"r"(A[1]),"r"(A[2]),"r"(A[3]),"r"(b0v),"r"(b1v))

#define LDM4(r, addr) asm volatile( \
    "ldmatrix.sync.aligned.m8n8.x4.shared.b16 {%0,%1,%2,%3}, [%4];" \
    : "=r"((r)[0]),"=r"((r)[1]),"=r"((r)[2]),"=r"((r)[3]) : "r"(addr))

// ---------------- encoders ----------------
__global__ void encode(const float* __restrict__ ex, const float* __restrict__ cx,
                       const float* __restrict__ Wew, const float* __restrict__ Web,
                       const float* __restrict__ Wcw, const float* __restrict__ Wcb) {
    int idx = blockIdx.x * blockDim.x + threadIdx.x;
    if (idx >= TWO_N * HD / 4) return;
    int c = (idx & 63) * 4;
    int g = idx >> 6;
    float4 v;
    if (g < NB) {
        const float* x = ex + (size_t)g * 5;
        v = ld4(&Web[c]);
        #pragma unroll
        for (int j = 0; j < 5; j++) v = f4fma(x[j], ld4(&Wew[j * HD + c]), v);
    } else {
        const float* x = cx + (size_t)(g - NB) * 3;
        v = ld4(&Wcb[c]);
        #pragma unroll
        for (int j = 0; j < 3; j++) v = f4fma(x[j], ld4(&Wcw[j * HD + c]), v);
    }
    size_t off = (size_t)g * HD + c;
    *(float4*)&g_h[off] = v;
    st_hi(off, v);
}

// ---------------- weight folding ----------------
__global__ __launch_bounds__(256, 2) void gemm_pre(const float* __restrict__ msg_w,
                                                   const float* __restrict__ upd_w) {
    int cb = blockIdx.x, rb = blockIdx.y, lh = blockIdx.z;
    int l = lh >> 1, h = lh & 1;
    int sec = cb >> 1;
    int col0 = (cb & 1) * 128;
    int row0 = rb * 128;
    const float* mh = msg_w + (size_t)(l*3 + h) * 512 * HD;
    const float* m2 = msg_w + (size_t)(l*3 + 2) * 512 * HD;
    const float* U1 = upd_w + (size_t)l * 512 * HD;
    const float* U2 = U1 + (size_t)HD * HD;
    const float* P1; const float* P2; float w1, w2, scale; int addU1;
    if (sec == 0)      { P1 = mh + HD*HD; w1 = 2.f; P2 = m2 + HD*HD; w2 = 1.f; scale = 1.f/3.f; addU1 = 1; }
    else if (sec == 1) { P1 = mh;          w1 = 1.f; P2 = 0;          w2 = 0.f; scale = 1.f/3.f; addU1 = 0; }
    else if (sec == 2) { P1 = m2;          w1 = 1.f; P2 = 0;          w2 = 0.f; scale = 1.f/3.f; addU1 = 0; }
    else               { P1 = mh + HD*HD; w1 = 1.f; P2 = m2 + HD*HD; w2 = 1.f; scale = 0.5f;    addU1 = 1; }

    __shared__ float As[2][16][132];
    __shared__ float Bs[2][16][128];
    int tid = threadIdx.x;
    int tx = tid & 15, ty = tid >> 4;
    int ar = tid >> 2, ak = (tid & 3) * 4;
    int bk = tid >> 5, bn = (tid & 31) * 4;

    float acc[8][8];
    #pragma unroll
    for (int i = 0; i < 8; i++)
        #pragma unroll
        for (int j = 0; j < 8; j++) acc[i][j] = 0.f;

    float4 a0v, a1v, b0v, b1v;
    {
        int r0 = row0 + ar, r1 = row0 + ar + 64;
        a0v = ld4(&P1[(size_t)r0*HD + ak]);
        a1v = ld4(&P1[(size_t)r1*HD + ak]);
        if (P2) { a0v = f4fma(w2/w1, ld4(&P2[(size_t)r0*HD + ak]), a0v);
                  a1v = f4fma(w2/w1, ld4(&P2[(size_t)r1*HD + ak]), a1v); }
        b0v = ld4(&U2[(size_t)bk*HD + col0 + bn]);
        b1v = ld4(&U2[(size_t)(bk+8)*HD + col0 + bn]);
    }
    As[0][ak+0][ar]=a0v.x; As[0][ak+1][ar]=a0v.y; As[0][ak+2][ar]=a0v.z; As[0][ak+3][ar]=a0v.w;
    As[0][ak+0][64+ar]=a1v.x; As[0][ak+1][64+ar]=a1v.y; As[0][ak+2][64+ar]=a1v.z; As[0][ak+3][64+ar]=a1v.w;
    *(float4*)&Bs[0][bk][bn] = b0v; *(float4*)&Bs[0][bk+8][bn] = b1v;
    __syncthreads();

    int buf = 0;
    #pragma unroll 1
    for (int t = 0; t < 16; t++) {
        if (t < 15) {
            int k0 = (t + 1) * 16;
            int r0 = row0 + ar, r1 = row0 + ar + 64;
            a0v = ld4(&P1[(size_t)r0*HD + k0 + ak]);
            a1v = ld4(&P1[(size_t)r1*HD + k0 + ak]);
            if (P2) { a0v = f4fma(w2/w1, ld4(&P2[(size_t)r0*HD + k0 + ak]), a0v);
                      a1v = f4fma(w2/w1, ld4(&P2[(size_t)r1*HD + k0 + ak]), a1v); }
            b0v = ld4(&U2[(size_t)(k0+bk)*HD + col0 + bn]);
            b1v = ld4(&U2[(size_t)(k0+bk+8)*HD + col0 + bn]);
        }
        #pragma unroll
        for (int k = 0; k < 16; k++) {
            float4 pa0 = *(float4*)&As[buf][k][ty*4];
            float4 pa1 = *(float4*)&As[buf][k][64 + ty*4];
            float4 pb0 = *(float4*)&Bs[buf][k][tx*4];
            float4 pb1 = *(float4*)&Bs[buf][k][64 + tx*4];
            float aa[8] = {pa0.x,pa0.y,pa0.z,pa0.w,pa1.x,pa1.y,pa1.z,pa1.w};
            float bb[8] = {pb0.x,pb0.y,pb0.z,pb0.w,pb1.x,pb1.y,pb1.z,pb1.w};
            #pragma unroll
            for (int i = 0; i < 8; i++)
                #pragma unroll
                for (int j = 0; j < 8; j++)
                    acc[i][j] = fmaf(aa[i], bb[j], acc[i][j]);
        }
        if (t < 15) {
            int nb2 = buf ^ 1;
            As[nb2][ak+0][ar]=a0v.x; As[nb2][ak+1][ar]=a0v.y; As[nb2][ak+2][ar]=a0v.z; As[nb2][ak+3][ar]=a0v.w;
            As[nb2][ak+0][64+ar]=a1v.x; As[nb2][ak+1][64+ar]=a1v.y; As[nb2][ak+2][64+ar]=a1v.z; As[nb2][ak+3][64+ar]=a1v.w;
            *(float4*)&Bs[nb2][bk][bn] = b0v; *(float4*)&Bs[nb2][bk+8][bn] = b1v;
        }
        __syncthreads();
        buf ^= 1;
    }

    float sc = w1 * scale;
    #pragma unroll
    for (int ih = 0; ih < 2; ih++)
        #pragma unroll
        for (int ii = 0; ii < 4; ii++) {
            int r = row0 + ih*64 + ty*4 + ii;          // k index
            #pragma unroll
            for (int jh = 0; jh < 2; jh++) {
                int c = col0 + jh*64 + tx*4;           // n index (within 256)
                float vv[4];
                #pragma unroll
                for (int j = 0; j < 4; j++) vv[j] = acc[ih*4+ii][jh*4+j] * sc;
                if (addU1) {
                    float4 u = ld4(&U1[(size_t)r*HD + c]);
                    vv[0]+=u.x; vv[1]+=u.y; vv[2]+=u.z; vv[3]+=u.w;
                }
                if (sec < 3) {
                    #pragma unroll
                    for (int j = 0; j < 4; j++) {
                        int n = sec*HD + c + j;
                        size_t o = ((size_t)lh*NWC + n)*HD + r;
                        __nv_bfloat16 hi = __float2bfloat16(vv[j]);
                        g_wth[o] = hi;
                        g_wtl[o] = __float2bfloat16(vv[j] - __bfloat162float(hi));
                    }
                } else {
                    float4 v = make_float4(vv[0],vv[1],vv[2],vv[3]);
                    *(float4*)&g_We[(size_t)lh*HD*HD + (size_t)r*HD + c] = v;
                }
            }
        }
}

// ---------------- bias folding ----------------
__global__ void bias_kernel(const float* __restrict__ msg_b,
                            const float* __restrict__ upd_w,
                            const float* __restrict__ upd_b) {
    int lh = blockIdx.x; int l = lh >> 1, h = lh & 1;
    int c = threadIdx.x;
    __shared__ float v1[HD], v2[HD];
    float mbh = msg_b[(l*3 + h)*HD + c];
    float mb2 = msg_b[(l*3 + 2)*HD + c];
    v1[c] = 2.f*mbh + mb2;
    v2[c] = mbh + mb2;
    __syncthreads();
    const float* U2 = upd_w + ((size_t)l*512 + HD) * HD;
    float s1 = 0.f, s2 = 0.f;
    for (int k = 0; k < HD; k++) {
        float u = U2[(size_t)k*HD + c];
        s1 += v1[k]*u; s2 += v2[k]*u;
    }
    g_bias [lh*HD + c] = s1*(1.f/3.f) + upd_b[l*HD + c];
    g_bias2[lh*HD + c] = s2*0.5f     + upd_b[l*HD + c];
}

// ---------------- tensor-core GEMM via mma.sync + ldmatrix ---------------
// C[128x128]/CTA; BK=32; 2-stage cp.async; 2 CTAs/SM.
// 2-product split: Ah@Bh + Ah@Bl (A=bf16(x); W kept exact as hi+lo).
// SMEM rows 80B: conflict-free for cp.async stores and ldmatrix reads.
#define MAT_SZ  10240            // 128 rows * 80 B
#define STG_TOT 30720            // AH | BH | BL
#define SMEM_MMA 67584           // max(2 stages = 61440, C stage 128*132*4)

__global__ __launch_bounds__(256, 2) void gemm_mma(int l) {
    extern __shared__ __align__(16) char sm[];
    uint32_t sb = smem_u32(sm);
    int tid = threadIdx.x, wid = tid >> 5, lane = tid & 31;
    int cb = blockIdx.x, rb = blockIdx.y, half = blockIdx.z;
    int lh = l*2 + half;
    const __nv_bfloat16* Axh = g_xh + (size_t)half*NB*HD;
    const __nv_bfloat16* Bwh = g_wth + (size_t)lh*NWC*HD;
    const __nv_bfloat16* Bwl = g_wtl + (size_t)lh*NWC*HD;

    // loader coords: thread -> (row lr0 / lr0+64, 16B segment lseg)
    int lr0 = tid >> 2, lseg = tid & 3;
    int an0 = rb*128 + lr0;      if (an0 >= NB) an0 = NB-1;
    int an1 = rb*128 + lr0 + 64; if (an1 >= NB) an1 = NB-1;
    int bn0 = cb*128 + lr0, bn1 = cb*128 + lr0 + 64;

    #define LOAD_STAGE(s, k0) do {                                             \
        uint32_t d0 = sb + (uint32_t)(s)*STG_TOT + lr0*80 + lseg*16;           \
        uint32_t d1 = d0 + 64*80;                                              \
        size_t ka = (size_t)(k0) + lseg*8;                                     \
        cpa16(d0,            Axh + (size_t)an0*HD + ka);                       \
        cpa16(d1,            Axh + (size_t)an1*HD + ka);                       \
        cpa16(d0 + MAT_SZ,   Bwh + (size_t)bn0*HD + ka);                       \
        cpa16(d1 + MAT_SZ,   Bwh + (size_t)bn1*HD + ka);                       \
        cpa16(d0 + 2*MAT_SZ, Bwl + (size_t)bn0*HD + ka);                       \
        cpa16(d1 + 2*MAT_SZ, Bwl + (size_t)bn1*HD + ka);                       \
        asm volatile("cp.async.commit_group;" ::: "memory");                   \
    } while (0)

    float acc[4][4][4];
    #pragma unroll
    for (int i = 0; i < 4; i++)
        #pragma unroll
        for (int j = 0; j < 4; j++)
            #pragma unroll
            for (int q = 0; q < 4; q++) acc[i][j][q] = 0.f;

    LOAD_STAGE(0, 0);
    LOAD_STAGE(1, 32);

    int warp_m = (wid >> 2) * 64, warp_n = (wid & 3) * 32;
    int la7 = lane & 7, lb8 = (lane >> 3) & 1, lhi = lane >> 4;
    // A ldmatrix.x4: mats = (m+0,k0-7)(m+8,k0-7)(m+0,k8-15)(m+8,k8-15)
    uint32_t aoff = (uint32_t)(warp_m + la7 + lb8*8)*80 + lhi*16;
    // B ldmatrix.x4: mats = (j,k0-7)(j,k8-15)(j+1,k0-7)(j+1,k8-15)
    uint32_t boff = MAT_SZ + (uint32_t)(warp_n + lhi*8 + la7)*80 + lb8*16;

    #pragma unroll 1
    for (int kt = 0; kt < 8; kt++) {
        if (kt < 7) asm volatile("cp.async.wait_group 1;" ::: "memory");
        else        asm volatile("cp.async.wait_group 0;" ::: "memory");
        __syncthreads();
        uint32_t stg = sb + (uint32_t)(kt & 1) * STG_TOT;
        #pragma unroll
        for (int k16 = 0; k16 < 2; k16++) {
            uint32_t ko = k16 * 32;
            uint32_t ah[4][4];
            #pragma unroll
            for (int i = 0; i < 4; i++)
                LDM4(ah[i], stg + aoff + i*1280 + ko);
            #pragma unroll
            for (int jj = 0; jj < 2; jj++) {
                uint32_t bh[4], bl[4];
                LDM4(bh, stg + boff + jj*1280 + ko);
                LDM4(bl, stg + MAT_SZ + boff + jj*1280 + ko);
                #pragma unroll
                for (int j2 = 0; j2 < 2; j2++) {
                    int j = jj*2 + j2;
                    #pragma unroll
                    for (int i = 0; i < 4; i++) {
                        MMA2(acc[i][j], ah[i], bh[j2*2], bh[j2*2+1]);
                        MMA2(acc[i][j], ah[i], bl[j2*2], bl[j2*2+1]);
                    }
                }
            }
        }
        __syncthreads();
        if (kt + 2 < 8) LOAD_STAGE(kt & 1, (kt + 2) * 32);
    }

    // epilogue: stage C through SMEM, coalesced store
    asm volatile("cp.async.wait_group 0;" ::: "memory");
    __syncthreads();
    float* Cs = (float*)sm;                    // 128 x 132 floats = 67584 B
    int g = lane >> 2;
    int ct = (lane & 3) * 2;
    #pragma unroll
    for (int i = 0; i < 4; i++)
        #pragma unroll
        for (int j = 0; j < 4; j++) {
            int r = warp_m + i*16 + g;
            int c = warp_n + j*8 + ct;
            *(float2*)&Cs[(size_t)r*132 + c]      = make_float2(acc[i][j][0], acc[i][j][1]);
            *(float2*)&Cs[(size_t)(r+8)*132 + c]  = make_float2(acc[i][j][2], acc[i][j][3]);
        }
    __syncthreads();
    #pragma unroll
    for (int it = 0; it < 16; it++) {
        int idx = tid + it*256;
        int r = idx >> 5, c4 = (idx & 31) * 4;
        int node = rb*128 + r;
        if (node < NB)
            *(float4*)&g_T[((size_t)(half*NB + node))*NWC + cb*128 + c4] = *(float4*)&Cs[(size_t)r*132 + c4];
    }
    #undef LOAD_STAGE
}

// ---------------- combine: u-sum + LN + GeLU + residual + bf16 cast -------
__global__ __launch_bounds__(256) void combine(int l,
        const float* __restrict__ ln_g, const float* __restrict__ ln_b) {
    int node = blockIdx.x * 8 + (threadIdx.x >> 5);
    int lane = threadIdx.x & 31;
    int half = node >= NB ? 1 : 0;
    int i = node - half * NB;
    int p = half ? node - NB : node + NB;
    int c0 = lane * 4, c1 = 128 + lane * 4;
    float4 u0, u1;

    if (i > 0 && i < NB - 1) {
        const float* tS  = g_T + (size_t)node * NWC;
        const float* tNm = g_T + (size_t)(node - 1) * NWC + 256;
        const float* tNp = g_T + (size_t)(node + 1) * NWC + 256;
        const float* tX  = g_T + (size_t)p * NWC + 512;
        const float* bi  = g_bias + (l*2 + half) * HD;
        u0 = f4add(f4add(ld4(tS+c0), ld4(tNm+c0)), f4add(ld4(tNp+c0), f4add(ld4(tX+c0), ld4(bi+c0))));
        u1 = f4add(f4add(ld4(tS+c1), ld4(tNm+c1)), f4add(ld4(tNp+c1), f4add(ld4(tX+c1), ld4(bi+c1))));
    } else {
        int nn = (i == 0) ? node + 1 : node - 1;
        const float* E  = g_We + (size_t)(l*2 + half) * HD * HD;
        const float* xg = g_h + (size_t)node * HD;
        float4 s0 = f4z(), s1 = f4z();
        #pragma unroll 4
        for (int k = 0; k < HD; k++) {
            float xv = xg[k];
            s0 = f4fma(xv, ld4(&E[(size_t)k*HD + c0]), s0);
            s1 = f4fma(xv, ld4(&E[(size_t)k*HD + c1]), s1);
        }
        const float* tN  = g_T + (size_t)nn * NWC + 256;
        const float* tX  = g_T + (size_t)p * NWC + 512;
        const float* bi2 = g_bias2 + (l*2 + half) * HD;
        u0 = f4add(s0, f4fma(1.5f, f4add(ld4(tN+c0), ld4(tX+c0)), ld4(bi2+c0)));
        u1 = f4add(s1, f4fma(1.5f, f4add(ld4(tN+c1), ld4(tX+c1)), ld4(bi2+c1)));
    }

    float s = u0.x+u0.y+u0.z+u0.w + u1.x+u1.y+u1.z+u1.w;
    float q = u0.x*u0.x+u0.y*u0.y+u0.z*u0.z+u0.w*u0.w
            + u1.x*u1.x+u1.y*u1.y+u1.z*u1.z+u1.w*u1.w;
    #pragma unroll
    for (int off = 16; off; off >>= 1) {
        s += __shfl_xor_sync(0xffffffff, s, off);
        q += __shfl_xor_sync(0xffffffff, q, off);
    }
    float mu = s * (1.f/HD);
    float rs = rsqrtf(q * (1.f/HD) - mu*mu + 1e-5f);

    const float* lg = ln_g + l*HD;
    const float* lb = ln_b + l*HD;
    float4 g0 = ld4(lg+c0), g1 = ld4(lg+c1);
    float4 b0 = ld4(lb+c0), b1 = ld4(lb+c1);
    size_t ho = (size_t)node * HD;
    float4 h0 = ld4(&g_h[ho+c0]), h1 = ld4(&g_h[ho+c1]);
    h0.x += gelu_exact((u0.x-mu)*rs*g0.x + b0.x);
    h0.y += gelu_exact((u0.y-mu)*rs*g0.y + b0.y);
    h0.z += gelu_exact((u0.z-mu)*rs*g0.z + b0.z);
    h0.w += gelu_exact((u0.w-mu)*rs*g0.w + b0.w);
    h1.x += gelu_exact((u1.x-mu)*rs*g1.x + b1.x);
    h1.y += gelu_exact((u1.y-mu)*rs*g1.y + b1.y);
    h1.z += gelu_exact((u1.z-mu)*rs*g1.z + b1.z);
    h1.w += gelu_exact((u1.w-mu)*rs*g1.w + b1.w);
    *(float4*)&g_h[ho+c0] = h0;
    *(float4*)&g_h[ho+c1] = h1;
    st_hi(ho+c0, h0);
    st_hi(ho+c1, h1);
}

// ---------------- readout ----------------
__global__ void zero_hm() { if (threadIdx.x < HD) g_hm[threadIdx.x] = 0.f; }

__global__ void colmean() {
    int c = threadIdx.x;
    int r0 = blockIdx.x * 200;
    float s = 0.f;
    for (int r = r0; r < r0 + 200; r++) s += g_h[(size_t)r * HD + c];
    atomicAdd(&g_hm[c], s);
}

__global__ void decoder(const float* __restrict__ dec1_w, const float* __restrict__ dec1_b,
                        const float* __restrict__ dec2_w, const float* __restrict__ dec2_b,
                        const float* __restrict__ Kp, const float* __restrict__ tau,
                        const float* __restrict__ tau_max, const float* __restrict__ lam,
                        float* __restrict__ out) {
    __shared__ float hm[HD], z[HD], red[64];
    int t = threadIdx.x;
    hm[t] = g_hm[t] * (1.0f / NB);
    __syncthreads();
    float acc = dec1_b[t];
    for (int k = 0; k < HD; k++) acc += hm[k] * dec1_w[k * HD + t];
    z[t] = gelu_exact(acc);
    __syncthreads();
    if (t < 128) {
        float a = dec2_b[t];
        for (int k = 0; k < HD; k++) a += z[k] * dec2_w[k * 128 + t];
        out[t] = a;
    }
    if (t < 64) {
        red[t] = Kp[t] * tau[t] / tau_max[t];
        out[129 + t] = Kp[t];
    }
    __syncthreads();
    if (t == 0) {
        float s = 0.f;
        for (int i = 0; i < 64; i++) s += red[i];
        out[128] = fabsf(lam[0]) - s;
    }
}

// ---------------- launch ----------------
extern "C" void kernel_launch(void* const* d_in, const int* in_sizes, int n_in,
                              void* d_out, int out_size) {
    const float* energy_x     = (const float*)d_in[0];
    const float* comm_x       = (const float*)d_in[1];
    const float* tau          = (const float*)d_in[2];
    const float* tau_max      = (const float*)d_in[3];
    const float* lambda_min_0 = (const float*)d_in[4];
    const float* We_w         = (const float*)d_in[5];
    const float* We_b         = (const float*)d_in[6];
    const float* Wc_w         = (const float*)d_in[7];
    const float* Wc_b         = (const float*)d_in[8];
    const float* msg_w        = (const float*)d_in[9];
    const float* msg_b        = (const float*)d_in[10];
    const float* upd_w        = (const float*)d_in[11];
    const float* upd_b        = (const float*)d_in[12];
    const float* ln_g         = (const float*)d_in[13];
    const float* ln_b         = (const float*)d_in[14];
    const float* dec1_w       = (const float*)d_in[15];
    const float* dec1_b       = (const float*)d_in[16];
    const float* dec2_w       = (const float*)d_in[17];
    const float* dec2_b       = (const float*)d_in[18];
    const float* K_param      = (const float*)d_in[19];
    float* out = (float*)d_out;

    cudaFuncSetAttribute(gemm_mma, cudaFuncAttributeMaxDynamicSharedMemorySize, SMEM_MMA);

    gemm_pre<<<dim3(8, 2, 8), 256>>>(msg_w, upd_w);
    bias_kernel<<<8, 256>>>(msg_b, upd_w, upd_b);
    encode<<<(TWO_N * HD / 4 + 255) / 256, 256>>>(energy_x, comm_x, We_w, We_b, Wc_w, Wc_b);

    for (int l = 0; l < NL; l++) {
        gemm_mma<<<dim3(6, (NB + 127) / 128, 2), 256, SMEM_MMA>>>(l);
        combine<<<TWO_N / 8, 256>>>(l, ln_g, ln_b);
    }

    zero_hm<<<1, 256>>>();
    colmean<<<100, 256>>>();
    decoder<<<1, 256>>>(dec1_w, dec1_b, dec2_w, dec2_b,
                        K_param, tau, tau_max, lambda_min_0, out);
}

// round 7
// speedup vs baseline: 5.6807x; 1.0370x over previous
#include <cuda_runtime.h>
#include <cuda_bf16.h>
#include <math.h>
#include <stdint.h>

#define NB 20000
#define HD 256
#define NL 4
#define TWO_N (2*NB)
#define NWC 768

// ---------------- device scratch ----------------
__device__ float g_h  [(size_t)TWO_N * HD];
__device__ __nv_bfloat16 g_xh[(size_t)TWO_N * HD];
__device__ __nv_bfloat16 g_T [(size_t)TWO_N * NWC];        // bf16 now
__device__ __nv_bfloat16 g_wth[(size_t)NL * 2 * NWC * HD]; // [lh][n][k]
__device__ __nv_bfloat16 g_wtl[(size_t)NL * 2 * NWC * HD];
__device__ float g_We [(size_t)NL * 2 * HD * HD];
__device__ float g_bias [NL * 2 * HD];
__device__ float g_bias2[NL * 2 * HD];
__device__ float g_hm [HD];

// ---------------- helpers ----------------
__device__ __forceinline__ float gelu_exact(float x) {
    return 0.5f * x * (1.0f + erff(x * 0.70710678118654752f));
}
__device__ __forceinline__ float4 ld4(const float* p) { return *(const float4*)p; }
__device__ __forceinline__ float4 f4z() { return make_float4(0.f,0.f,0.f,0.f); }
__device__ __forceinline__ float4 f4add(float4 a, float4 b) {
    return make_float4(a.x+b.x, a.y+b.y, a.z+b.z, a.w+b.w);
}
__device__ __forceinline__ float4 f4fma(float s, float4 a, float4 b) {
    return make_float4(fmaf(s,a.x,b.x), fmaf(s,a.y,b.y), fmaf(s,a.z,b.z), fmaf(s,a.w,b.w));
}
__device__ __forceinline__ float4 ld4bf(const __nv_bfloat16* p) {
    uint2 u = *(const uint2*)p;
    float4 r;
    r.x = __uint_as_float(u.x << 16);
    r.y = __uint_as_float(u.x & 0xffff0000u);
    r.z = __uint_as_float(u.y << 16);
    r.w = __uint_as_float(u.y & 0xffff0000u);
    return r;
}
__device__ __forceinline__ uint32_t smem_u32(const void* p) {
    uint32_t a;
    asm("{ .reg .u64 t; cvta.to.shared.u64 t, %1; cvt.u32.u64 %0, t; }" : "=r"(a) : "l"(p));
    return a;
}
__device__ __forceinline__ void cpa16(uint32_t s, const void* g) {
    asm volatile("cp.async.cg.shared.global [%0], [%1], 16;" :: "r"(s), "l"(g));
}
__device__ __forceinline__ void st_hi(size_t off, float4 v) {
    __nv_bfloat162* ph = (__nv_bfloat162*)&g_xh[off];
    ph[0] = __nv_bfloat162(__float2bfloat16(v.x), __float2bfloat16(v.y));
    ph[1] = __nv_bfloat162(__float2bfloat16(v.z), __float2bfloat16(v.w));
}

#define MMA2(c, A, b0v, b1v) asm volatile( \
    "mma.sync.aligned.m16n8k16.row.col.f32.bf16.bf16.f32 " \
    "{%0,%1,%2,%3},{%4,%5,%6,%7},{%8,%9},{%0,%1,%2,%3};" \
    : "+f"(c[0]),"+f"(c[1]),"+f"(c[2]),"+f"(c[3]) \
    : "r"(A[0]),"r"(A[1]),"r"(A[2]),"r"(A[3]),"r"(b0v),"r"(b1v))

#define LDM4(r, addr) asm volatile( \
    "ldmatrix.sync.aligned.m8n8.x4.shared.b16 {%0,%1,%2,%3}, [%4];" \
    : "=r"((r)[0]),"=r"((r)[1]),"=r"((r)[2]),"=r"((r)[3]) : "r"(addr))

// ---------------- encoders ----------------
__global__ void encode(const float* __restrict__ ex, const float* __restrict__ cx,
                       const float* __restrict__ Wew, const float* __restrict__ Web,
                       const float* __restrict__ Wcw, const float* __restrict__ Wcb) {
    int idx = blockIdx.x * blockDim.x + threadIdx.x;
    if (idx >= TWO_N * HD / 4) return;
    int c = (idx & 63) * 4;
    int g = idx >> 6;
    float4 v;
    if (g < NB) {
        const float* x = ex + (size_t)g * 5;
        v = ld4(&Web[c]);
        #pragma unroll
        for (int j = 0; j < 5; j++) v = f4fma(x[j], ld4(&Wew[j * HD + c]), v);
    } else {
        const float* x = cx + (size_t)(g - NB) * 3;
        v = ld4(&Wcb[c]);
        #pragma unroll
        for (int j = 0; j < 3; j++) v = f4fma(x[j], ld4(&Wcw[j * HD + c]), v);
    }
    size_t off = (size_t)g * HD + c;
    *(float4*)&g_h[off] = v;
    st_hi(off, v);
}

// ---------------- weight folding ----------------
__global__ __launch_bounds__(256, 2) void gemm_pre(const float* __restrict__ msg_w,
                                                   const float* __restrict__ upd_w) {
    int cb = blockIdx.x, rb = blockIdx.y, lh = blockIdx.z;
    int l = lh >> 1, h = lh & 1;
    int sec = cb >> 1;
    int col0 = (cb & 1) * 128;
    int row0 = rb * 128;
    const float* mh = msg_w + (size_t)(l*3 + h) * 512 * HD;
    const float* m2 = msg_w + (size_t)(l*3 + 2) * 512 * HD;
    const float* U1 = upd_w + (size_t)l * 512 * HD;
    const float* U2 = U1 + (size_t)HD * HD;
    const float* P1; const float* P2; float w1, w2, scale; int addU1;
    if (sec == 0)      { P1 = mh + HD*HD; w1 = 2.f; P2 = m2 + HD*HD; w2 = 1.f; scale = 1.f/3.f; addU1 = 1; }
    else if (sec == 1) { P1 = mh;          w1 = 1.f; P2 = 0;          w2 = 0.f; scale = 1.f/3.f; addU1 = 0; }
    else if (sec == 2) { P1 = m2;          w1 = 1.f; P2 = 0;          w2 = 0.f; scale = 1.f/3.f; addU1 = 0; }
    else               { P1 = mh + HD*HD; w1 = 1.f; P2 = m2 + HD*HD; w2 = 1.f; scale = 0.5f;    addU1 = 1; }

    __shared__ float As[2][16][132];
    __shared__ float Bs[2][16][128];
    int tid = threadIdx.x;
    int tx = tid & 15, ty = tid >> 4;
    int ar = tid >> 2, ak = (tid & 3) * 4;
    int bk = tid >> 5, bn = (tid & 31) * 4;

    float acc[8][8];
    #pragma unroll
    for (int i = 0; i < 8; i++)
        #pragma unroll
        for (int j = 0; j < 8; j++) acc[i][j] = 0.f;

    float4 a0v, a1v, b0v, b1v;
    {
        int r0 = row0 + ar, r1 = row0 + ar + 64;
        a0v = ld4(&P1[(size_t)r0*HD + ak]);
        a1v = ld4(&P1[(size_t)r1*HD + ak]);
        if (P2) { a0v = f4fma(w2/w1, ld4(&P2[(size_t)r0*HD + ak]), a0v);
                  a1v = f4fma(w2/w1, ld4(&P2[(size_t)r1*HD + ak]), a1v); }
        b0v = ld4(&U2[(size_t)bk*HD + col0 + bn]);
        b1v = ld4(&U2[(size_t)(bk+8)*HD + col0 + bn]);
    }
    As[0][ak+0][ar]=a0v.x; As[0][ak+1][ar]=a0v.y; As[0][ak+2][ar]=a0v.z; As[0][ak+3][ar]=a0v.w;
    As[0][ak+0][64+ar]=a1v.x; As[0][ak+1][64+ar]=a1v.y; As[0][ak+2][64+ar]=a1v.z; As[0][ak+3][64+ar]=a1v.w;
    *(float4*)&Bs[0][bk][bn] = b0v; *(float4*)&Bs[0][bk+8][bn] = b1v;
    __syncthreads();

    int buf = 0;
    #pragma unroll 1
    for (int t = 0; t < 16; t++) {
        if (t < 15) {
            int k0 = (t + 1) * 16;
            int r0 = row0 + ar, r1 = row0 + ar + 64;
            a0v = ld4(&P1[(size_t)r0*HD + k0 + ak]);
            a1v = ld4(&P1[(size_t)r1*HD + k0 + ak]);
            if (P2) { a0v = f4fma(w2/w1, ld4(&P2[(size_t)r0*HD + k0 + ak]), a0v);
                      a1v = f4fma(w2/w1, ld4(&P2[(size_t)r1*HD + k0 + ak]), a1v); }
            b0v = ld4(&U2[(size_t)(k0+bk)*HD + col0 + bn]);
            b1v = ld4(&U2[(size_t)(k0+bk+8)*HD + col0 + bn]);
        }
        #pragma unroll
        for (int k = 0; k < 16; k++) {
            float4 pa0 = *(float4*)&As[buf][k][ty*4];
            float4 pa1 = *(float4*)&As[buf][k][64 + ty*4];
            float4 pb0 = *(float4*)&Bs[buf][k][tx*4];
            float4 pb1 = *(float4*)&Bs[buf][k][64 + tx*4];
            float aa[8] = {pa0.x,pa0.y,pa0.z,pa0.w,pa1.x,pa1.y,pa1.z,pa1.w};
            float bb[8] = {pb0.x,pb0.y,pb0.z,pb0.w,pb1.x,pb1.y,pb1.z,pb1.w};
            #pragma unroll
            for (int i = 0; i < 8; i++)
                #pragma unroll
                for (int j = 0; j < 8; j++)
                    acc[i][j] = fmaf(aa[i], bb[j], acc[i][j]);
        }
        if (t < 15) {
            int nb2 = buf ^ 1;
            As[nb2][ak+0][ar]=a0v.x; As[nb2][ak+1][ar]=a0v.y; As[nb2][ak+2][ar]=a0v.z; As[nb2][ak+3][ar]=a0v.w;
            As[nb2][ak+0][64+ar]=a1v.x; As[nb2][ak+1][64+ar]=a1v.y; As[nb2][ak+2][64+ar]=a1v.z; As[nb2][ak+3][64+ar]=a1v.w;
            *(float4*)&Bs[nb2][bk][bn] = b0v; *(float4*)&Bs[nb2][bk+8][bn] = b1v;
        }
        __syncthreads();
        buf ^= 1;
    }

    float sc = w1 * scale;
    #pragma unroll
    for (int ih = 0; ih < 2; ih++)
        #pragma unroll
        for (int ii = 0; ii < 4; ii++) {
            int r = row0 + ih*64 + ty*4 + ii;          // k index
            #pragma unroll
            for (int jh = 0; jh < 2; jh++) {
                int c = col0 + jh*64 + tx*4;           // n index (within 256)
                float vv[4];
                #pragma unroll
                for (int j = 0; j < 4; j++) vv[j] = acc[ih*4+ii][jh*4+j] * sc;
                if (addU1) {
                    float4 u = ld4(&U1[(size_t)r*HD + c]);
                    vv[0]+=u.x; vv[1]+=u.y; vv[2]+=u.z; vv[3]+=u.w;
                }
                if (sec < 3) {
                    #pragma unroll
                    for (int j = 0; j < 4; j++) {
                        int n = sec*HD + c + j;
                        size_t o = ((size_t)lh*NWC + n)*HD + r;
                        __nv_bfloat16 hi = __float2bfloat16(vv[j]);
                        g_wth[o] = hi;
                        g_wtl[o] = __float2bfloat16(vv[j] - __bfloat162float(hi));
                    }
                } else {
                    float4 v = make_float4(vv[0],vv[1],vv[2],vv[3]);
                    *(float4*)&g_We[(size_t)lh*HD*HD + (size_t)r*HD + c] = v;
                }
            }
        }
}

// ---------------- bias folding ----------------
__global__ void bias_kernel(const float* __restrict__ msg_b,
                            const float* __restrict__ upd_w,
                            const float* __restrict__ upd_b) {
    int lh = blockIdx.x; int l = lh >> 1, h = lh & 1;
    int c = threadIdx.x;
    __shared__ float v1[HD], v2[HD];
    float mbh = msg_b[(l*3 + h)*HD + c];
    float mb2 = msg_b[(l*3 + 2)*HD + c];
    v1[c] = 2.f*mbh + mb2;
    v2[c] = mbh + mb2;
    __syncthreads();
    const float* U2 = upd_w + ((size_t)l*512 + HD) * HD;
    float s1 = 0.f, s2 = 0.f;
    for (int k = 0; k < HD; k++) {
        float u = U2[(size_t)k*HD + c];
        s1 += v1[k]*u; s2 += v2[k]*u;
    }
    g_bias [lh*HD + c] = s1*(1.f/3.f) + upd_b[l*HD + c];
    g_bias2[lh*HD + c] = s2*0.5f     + upd_b[l*HD + c];
}

// ---------------- tensor-core GEMM via mma.sync + ldmatrix ---------------
// C[128x128]/CTA; BK=32; 3-stage cp.async, 1 barrier/iter; 2 CTAs/SM.
// 2-product split: Ah@Bh + Ah@Bl. bf16 output. 80B smem rows (conflict-free).
#define MAT_SZ  10240            // 128 rows * 80 B
#define STG_TOT 30720            // AH | BH | BL
#define SMEM_MMA 92160           // 3 stages (C stage 67584 fits inside)

__global__ __launch_bounds__(256, 2) void gemm_mma(int l) {
    extern __shared__ __align__(16) char sm[];
    uint32_t sb = smem_u32(sm);
    int tid = threadIdx.x, wid = tid >> 5, lane = tid & 31;
    int cb = blockIdx.x, rb = blockIdx.y, half = blockIdx.z;
    int lh = l*2 + half;
    const __nv_bfloat16* Axh = g_xh + (size_t)half*NB*HD;
    const __nv_bfloat16* Bwh = g_wth + (size_t)lh*NWC*HD;
    const __nv_bfloat16* Bwl = g_wtl + (size_t)lh*NWC*HD;

    // loader coords: thread -> (row lr0 / lr0+64, 16B segment lseg)
    int lr0 = tid >> 2, lseg = tid & 3;
    int an0 = rb*128 + lr0;      if (an0 >= NB) an0 = NB-1;
    int an1 = rb*128 + lr0 + 64; if (an1 >= NB) an1 = NB-1;
    int bn0 = cb*128 + lr0, bn1 = cb*128 + lr0 + 64;

    #define LOAD_STAGE(s, k0) do {                                             \
        uint32_t d0 = sb + (uint32_t)(s)*STG_TOT + lr0*80 + lseg*16;           \
        uint32_t d1 = d0 + 64*80;                                              \
        size_t ka = (size_t)(k0) + lseg*8;                                     \
        cpa16(d0,            Axh + (size_t)an0*HD + ka);                       \
        cpa16(d1,            Axh + (size_t)an1*HD + ka);                       \
        cpa16(d0 + MAT_SZ,   Bwh + (size_t)bn0*HD + ka);                       \
        cpa16(d1 + MAT_SZ,   Bwh + (size_t)bn1*HD + ka);                       \
        cpa16(d0 + 2*MAT_SZ, Bwl + (size_t)bn0*HD + ka);                       \
        cpa16(d1 + 2*MAT_SZ, Bwl + (size_t)bn1*HD + ka);                       \
        asm volatile("cp.async.commit_group;" ::: "memory");                   \
    } while (0)

    float acc[4][4][4];
    #pragma unroll
    for (int i = 0; i < 4; i++)
        #pragma unroll
        for (int j = 0; j < 4; j++)
            #pragma unroll
            for (int q = 0; q < 4; q++) acc[i][j][q] = 0.f;

    LOAD_STAGE(0, 0);
    LOAD_STAGE(1, 32);

    int warp_m = (wid >> 2) * 64, warp_n = (wid & 3) * 32;
    int la7 = lane & 7, lb8 = (lane >> 3) & 1, lhi = lane >> 4;
    uint32_t aoff = (uint32_t)(warp_m + la7 + lb8*8)*80 + lhi*16;
    uint32_t boff = MAT_SZ + (uint32_t)(warp_n + lhi*8 + la7)*80 + lb8*16;

    int stage = 0;
    #pragma unroll 1
    for (int kt = 0; kt < 8; kt++) {
        if (kt < 7) asm volatile("cp.async.wait_group 1;" ::: "memory");
        else        asm volatile("cp.async.wait_group 0;" ::: "memory");
        __syncthreads();
        if (kt + 2 < 8) {
            int s2 = stage + 2; if (s2 >= 3) s2 -= 3;
            LOAD_STAGE(s2, (kt + 2) * 32);
        }
        uint32_t stg = sb + (uint32_t)stage * STG_TOT;
        #pragma unroll
        for (int k16 = 0; k16 < 2; k16++) {
            uint32_t ko = k16 * 32;
            uint32_t ah[4][4];
            #pragma unroll
            for (int i = 0; i < 4; i++)
                LDM4(ah[i], stg + aoff + i*1280 + ko);
            #pragma unroll
            for (int jj = 0; jj < 2; jj++) {
                uint32_t bh[4], bl[4];
                LDM4(bh, stg + boff + jj*1280 + ko);
                LDM4(bl, stg + MAT_SZ + boff + jj*1280 + ko);
                // 8 independent bh-MMAs, then 8 bl-MMAs (dep distance 8)
                #pragma unroll
                for (int i = 0; i < 4; i++) MMA2(acc[i][jj*2],   ah[i], bh[0], bh[1]);
                #pragma unroll
                for (int i = 0; i < 4; i++) MMA2(acc[i][jj*2+1], ah[i], bh[2], bh[3]);
                #pragma unroll
                for (int i = 0; i < 4; i++) MMA2(acc[i][jj*2],   ah[i], bl[0], bl[1]);
                #pragma unroll
                for (int i = 0; i < 4; i++) MMA2(acc[i][jj*2+1], ah[i], bl[2], bl[3]);
            }
        }
        stage++; if (stage >= 3) stage = 0;
    }

    // epilogue: stage C through SMEM (fp32), store bf16 coalesced
    __syncthreads();
    float* Cs = (float*)sm;                    // 128 x 132 floats
    int g = lane >> 2;
    int ct = (lane & 3) * 2;
    #pragma unroll
    for (int i = 0; i < 4; i++)
        #pragma unroll
        for (int j = 0; j < 4; j++) {
            int r = warp_m + i*16 + g;
            int c = warp_n + j*8 + ct;
            *(float2*)&Cs[(size_t)r*132 + c]      = make_float2(acc[i][j][0], acc[i][j][1]);
            *(float2*)&Cs[(size_t)(r+8)*132 + c]  = make_float2(acc[i][j][2], acc[i][j][3]);
        }
    __syncthreads();
    #pragma unroll
    for (int it = 0; it < 16; it++) {
        int idx = tid + it*256;
        int r = idx >> 5, c4 = (idx & 31) * 4;
        int node = rb*128 + r;
        if (node < NB) {
            float4 v = *(float4*)&Cs[(size_t)r*132 + c4];
            __nv_bfloat162 p0 = __nv_bfloat162(__float2bfloat16(v.x), __float2bfloat16(v.y));
            __nv_bfloat162 p1 = __nv_bfloat162(__float2bfloat16(v.z), __float2bfloat16(v.w));
            uint2 pk;
            pk.x = *(uint32_t*)&p0; pk.y = *(uint32_t*)&p1;
            *(uint2*)&g_T[((size_t)(half*NB + node))*NWC + cb*128 + c4] = pk;
        }
    }
    #undef LOAD_STAGE
}

// ---------------- combine: u-sum + LN + GeLU + residual + bf16 cast -------
__global__ __launch_bounds__(256) void combine(int l,
        const float* __restrict__ ln_g, const float* __restrict__ ln_b) {
    int node = blockIdx.x * 8 + (threadIdx.x >> 5);
    int lane = threadIdx.x & 31;
    int half = node >= NB ? 1 : 0;
    int i = node - half * NB;
    int p = half ? node - NB : node + NB;
    int c0 = lane * 4, c1 = 128 + lane * 4;
    float4 u0, u1;

    if (i > 0 && i < NB - 1) {
        const __nv_bfloat16* tS  = g_T + (size_t)node * NWC;
        const __nv_bfloat16* tNm = g_T + (size_t)(node - 1) * NWC + 256;
        const __nv_bfloat16* tNp = g_T + (size_t)(node + 1) * NWC + 256;
        const __nv_bfloat16* tX  = g_T + (size_t)p * NWC + 512;
        const float* bi  = g_bias + (l*2 + half) * HD;
        u0 = f4add(f4add(ld4bf(tS+c0), ld4bf(tNm+c0)),
                   f4add(ld4bf(tNp+c0), f4add(ld4bf(tX+c0), ld4(bi+c0))));
        u1 = f4add(f4add(ld4bf(tS+c1), ld4bf(tNm+c1)),
                   f4add(ld4bf(tNp+c1), f4add(ld4bf(tX+c1), ld4(bi+c1))));
    } else {
        int nn = (i == 0) ? node + 1 : node - 1;
        const float* E  = g_We + (size_t)(l*2 + half) * HD * HD;
        const float* xg = g_h + (size_t)node * HD;
        float4 s0 = f4z(), s1 = f4z();
        #pragma unroll 4
        for (int k = 0; k < HD; k++) {
            float xv = xg[k];
            s0 = f4fma(xv, ld4(&E[(size_t)k*HD + c0]), s0);
            s1 = f4fma(xv, ld4(&E[(size_t)k*HD + c1]), s1);
        }
        const __nv_bfloat16* tN = g_T + (size_t)nn * NWC + 256;
        const __nv_bfloat16* tX = g_T + (size_t)p * NWC + 512;
        const float* bi2 = g_bias2 + (l*2 + half) * HD;
        u0 = f4add(s0, f4fma(1.5f, f4add(ld4bf(tN+c0), ld4bf(tX+c0)), ld4(bi2+c0)));
        u1 = f4add(s1, f4fma(1.5f, f4add(ld4bf(tN+c1), ld4bf(tX+c1)), ld4(bi2+c1)));
    }

    float s = u0.x+u0.y+u0.z+u0.w + u1.x+u1.y+u1.z+u1.w;
    float q = u0.x*u0.x+u0.y*u0.y+u0.z*u0.z+u0.w*u0.w
            + u1.x*u1.x+u1.y*u1.y+u1.z*u1.z+u1.w*u1.w;
    #pragma unroll
    for (int off = 16; off; off >>= 1) {
        s += __shfl_xor_sync(0xffffffff, s, off);
        q += __shfl_xor_sync(0xffffffff, q, off);
    }
    float mu = s * (1.f/HD);
    float rs = rsqrtf(q * (1.f/HD) - mu*mu + 1e-5f);

    const float* lg = ln_g + l*HD;
    const float* lb = ln_b + l*HD;
    float4 g0 = ld4(lg+c0), g1 = ld4(lg+c1);
    float4 b0 = ld4(lb+c0), b1 = ld4(lb+c1);
    size_t ho = (size_t)node * HD;
    float4 h0 = ld4(&g_h[ho+c0]), h1 = ld4(&g_h[ho+c1]);
    h0.x += gelu_exact((u0.x-mu)*rs*g0.x + b0.x);
    h0.y += gelu_exact((u0.y-mu)*rs*g0.y + b0.y);
    h0.z += gelu_exact((u0.z-mu)*rs*g0.z + b0.z);
    h0.w += gelu_exact((u0.w-mu)*rs*g0.w + b0.w);
    h1.x += gelu_exact((u1.x-mu)*rs*g1.x + b1.x);
    h1.y += gelu_exact((u1.y-mu)*rs*g1.y + b1.y);
    h1.z += gelu_exact((u1.z-mu)*rs*g1.z + b1.z);
    h1.w += gelu_exact((u1.w-mu)*rs*g1.w + b1.w);
    *(float4*)&g_h[ho+c0] = h0;
    *(float4*)&g_h[ho+c1] = h1;
    st_hi(ho+c0, h0);
    st_hi(ho+c1, h1);
}

// ---------------- readout ----------------
__global__ void zero_hm() { if (threadIdx.x < HD) g_hm[threadIdx.x] = 0.f; }

__global__ void colmean() {
    int c = threadIdx.x;
    int r0 = blockIdx.x * 200;
    float s = 0.f;
    for (int r = r0; r < r0 + 200; r++) s += g_h[(size_t)r * HD + c];
    atomicAdd(&g_hm[c], s);
}

__global__ void decoder(const float* __restrict__ dec1_w, const float* __restrict__ dec1_b,
                        const float* __restrict__ dec2_w, const float* __restrict__ dec2_b,
                        const float* __restrict__ Kp, const float* __restrict__ tau,
                        const float* __restrict__ tau_max, const float* __restrict__ lam,
                        float* __restrict__ out) {
    __shared__ float hm[HD], z[HD], red[64];
    int t = threadIdx.x;
    hm[t] = g_hm[t] * (1.0f / NB);
    __syncthreads();
    float acc = dec1_b[t];
    for (int k = 0; k < HD; k++) acc += hm[k] * dec1_w[k * HD + t];
    z[t] = gelu_exact(acc);
    __syncthreads();
    if (t < 128) {
        float a = dec2_b[t];
        for (int k = 0; k < HD; k++) a += z[k] * dec2_w[k * 128 + t];
        out[t] = a;
    }
    if (t < 64) {
        red[t] = Kp[t] * tau[t] / tau_max[t];
        out[129 + t] = Kp[t];
    }
    __syncthreads();
    if (t == 0) {
        float s = 0.f;
        for (int i = 0; i < 64; i++) s += red[i];
        out[128] = fabsf(lam[0]) - s;
    }
}

// ---------------- launch ----------------
extern "C" void kernel_launch(void* const* d_in, const int* in_sizes, int n_in,
                              void* d_out, int out_size) {
    const float* energy_x     = (const float*)d_in[0];
    const float* comm_x       = (const float*)d_in[1];
    const float* tau          = (const float*)d_in[2];
    const float* tau_max      = (const float*)d_in[3];
    const float* lambda_min_0 = (const float*)d_in[4];
    const float* We_w         = (const float*)d_in[5];
    const float* We_b         = (const float*)d_in[6];
    const float* Wc_w         = (const float*)d_in[7];
    const float* Wc_b         = (const float*)d_in[8];
    const float* msg_w        = (const float*)d_in[9];
    const float* msg_b        = (const float*)d_in[10];
    const float* upd_w        = (const float*)d_in[11];
    const float* upd_b        = (const float*)d_in[12];
    const float* ln_g         = (const float*)d_in[13];
    const float* ln_b         = (const float*)d_in[14];
    const float* dec1_w       = (const float*)d_in[15];
    const float* dec1_b       = (const float*)d_in[16];
    const float* dec2_w       = (const float*)d_in[17];
    const float* dec2_b       = (const float*)d_in[18];
    const float* K_param      = (const float*)d_in[19];
    float* out = (float*)d_out;

    cudaFuncSetAttribute(gemm_mma, cudaFuncAttributeMaxDynamicSharedMemorySize, SMEM_MMA);

    gemm_pre<<<dim3(8, 2, 8), 256>>>(msg_w, upd_w);
    bias_kernel<<<8, 256>>>(msg_b, upd_w, upd_b);
    encode<<<(TWO_N * HD / 4 + 255) / 256, 256>>>(energy_x, comm_x, We_w, We_b, Wc_w, Wc_b);

    for (int l = 0; l < NL; l++) {
        gemm_mma<<<dim3(6, (NB + 127) / 128, 2), 256, SMEM_MMA>>>(l);
        combine<<<TWO_N / 8, 256>>>(l, ln_g, ln_b);
    }

    zero_hm<<<1, 256>>>();
    colmean<<<100, 256>>>();
    decoder<<<1, 256>>>(dec1_w, dec1_b, dec2_w, dec2_b,
                        K_param, tau, tau_max, lambda_min_0, out);
}

// round 8
// speedup vs baseline: 6.0011x; 1.0564x over previous
#include <cuda_runtime.h>
#include <cuda_bf16.h>
#include <math.h>
#include <stdint.h>

#define NB 20000
#define HD 256
#define NL 4
#define TWO_N (2*NB)
#define NWC 768

// ---------------- device scratch ----------------
__device__ __nv_bfloat16 g_xh[(size_t)TWO_N * HD];          // h (bf16, sole copy)
__device__ __nv_bfloat16 g_T [(size_t)TWO_N * NWC];         // projections bf16
__device__ __nv_bfloat16 g_wth[(size_t)NL * 2 * NWC * HD];  // [lh][n][k]
__device__ __nv_bfloat16 g_wtl[(size_t)NL * 2 * NWC * HD];
__device__ float g_We [(size_t)NL * 2 * HD * HD];
__device__ float g_bias [NL * 2 * HD];
__device__ float g_bias2[NL * 2 * HD];
__device__ float g_hm [HD];

// ---------------- helpers ----------------
__device__ __forceinline__ float gelu_exact(float x) {
    return 0.5f * x * (1.0f + erff(x * 0.70710678118654752f));
}
__device__ __forceinline__ float4 ld4(const float* p) { return *(const float4*)p; }
__device__ __forceinline__ float4 f4z() { return make_float4(0.f,0.f,0.f,0.f); }
__device__ __forceinline__ float4 f4add(float4 a, float4 b) {
    return make_float4(a.x+b.x, a.y+b.y, a.z+b.z, a.w+b.w);
}
__device__ __forceinline__ float4 f4fma(float s, float4 a, float4 b) {
    return make_float4(fmaf(s,a.x,b.x), fmaf(s,a.y,b.y), fmaf(s,a.z,b.z), fmaf(s,a.w,b.w));
}
__device__ __forceinline__ float4 ld4bf(const __nv_bfloat16* p) {
    uint2 u = *(const uint2*)p;
    float4 r;
    r.x = __uint_as_float(u.x << 16);
    r.y = __uint_as_float(u.x & 0xffff0000u);
    r.z = __uint_as_float(u.y << 16);
    r.w = __uint_as_float(u.y & 0xffff0000u);
    return r;
}
__device__ __forceinline__ uint32_t smem_u32(const void* p) {
    uint32_t a;
    asm("{ .reg .u64 t; cvta.to.shared.u64 t, %1; cvt.u32.u64 %0, t; }" : "=r"(a) : "l"(p));
    return a;
}
__device__ __forceinline__ void cpa16(uint32_t s, const void* g) {
    asm volatile("cp.async.cg.shared.global [%0], [%1], 16;" :: "r"(s), "l"(g));
}
__device__ __forceinline__ void st_hi(size_t off, float4 v) {
    __nv_bfloat162* ph = (__nv_bfloat162*)&g_xh[off];
    ph[0] = __nv_bfloat162(__float2bfloat16(v.x), __float2bfloat16(v.y));
    ph[1] = __nv_bfloat162(__float2bfloat16(v.z), __float2bfloat16(v.w));
}

#define MMA2(c, A, b0v, b1v) asm volatile( \
    "mma.sync.aligned.m16n8k16.row.col.f32.bf16.bf16.f32 " \
    "{%0,%1,%2,%3},{%4,%5,%6,%7},{%8,%9},{%0,%1,%2,%3};" \
    : "+f"(c[0]),"+f"(c[1]),"+f"(c[2]),"+f"(c[3]) \
    : "r"(A[0]),"r"(A[1]),"r"(A[2]),"r"(A[3]),"r"(b0v),"r"(b1v))

#define LDM4(r, addr) asm volatile( \
    "ldmatrix.sync.aligned.m8n8.x4.shared.b16 {%0,%1,%2,%3}, [%4];" \
    : "=r"((r)[0]),"=r"((r)[1]),"=r"((r)[2]),"=r"((r)[3]) : "r"(addr))

// ---------------- encoders ----------------
__global__ void encode(const float* __restrict__ ex, const float* __restrict__ cx,
                       const float* __restrict__ Wew, const float* __restrict__ Web,
                       const float* __restrict__ Wcw, const float* __restrict__ Wcb) {
    int idx = blockIdx.x * blockDim.x + threadIdx.x;
    if (idx >= TWO_N * HD / 4) return;
    int c = (idx & 63) * 4;
    int g = idx >> 6;
    float4 v;
    if (g < NB) {
        const float* x = ex + (size_t)g * 5;
        v = ld4(&Web[c]);
        #pragma unroll
        for (int j = 0; j < 5; j++) v = f4fma(x[j], ld4(&Wew[j * HD + c]), v);
    } else {
        const float* x = cx + (size_t)(g - NB) * 3;
        v = ld4(&Wcb[c]);
        #pragma unroll
        for (int j = 0; j < 3; j++) v = f4fma(x[j], ld4(&Wcw[j * HD + c]), v);
    }
    st_hi((size_t)g * HD + c, v);
}

// ---------------- weight folding ----------------
__global__ __launch_bounds__(256, 2) void gemm_pre(const float* __restrict__ msg_w,
                                                   const float* __restrict__ upd_w) {
    int cb = blockIdx.x, rb = blockIdx.y, lh = blockIdx.z;
    int l = lh >> 1, h = lh & 1;
    int sec = cb >> 1;
    int col0 = (cb & 1) * 128;
    int row0 = rb * 128;
    const float* mh = msg_w + (size_t)(l*3 + h) * 512 * HD;
    const float* m2 = msg_w + (size_t)(l*3 + 2) * 512 * HD;
    const float* U1 = upd_w + (size_t)l * 512 * HD;
    const float* U2 = U1 + (size_t)HD * HD;
    const float* P1; const float* P2; float w1, w2, scale; int addU1;
    if (sec == 0)      { P1 = mh + HD*HD; w1 = 2.f; P2 = m2 + HD*HD; w2 = 1.f; scale = 1.f/3.f; addU1 = 1; }
    else if (sec == 1) { P1 = mh;          w1 = 1.f; P2 = 0;          w2 = 0.f; scale = 1.f/3.f; addU1 = 0; }
    else if (sec == 2) { P1 = m2;          w1 = 1.f; P2 = 0;          w2 = 0.f; scale = 1.f/3.f; addU1 = 0; }
    else               { P1 = mh + HD*HD; w1 = 1.f; P2 = m2 + HD*HD; w2 = 1.f; scale = 0.5f;    addU1 = 1; }

    __shared__ float As[2][16][132];
    __shared__ float Bs[2][16][128];
    int tid = threadIdx.x;
    int tx = tid & 15, ty = tid >> 4;
    int ar = tid >> 2, ak = (tid & 3) * 4;
    int bk = tid >> 5, bn = (tid & 31) * 4;

    float acc[8][8];
    #pragma unroll
    for (int i = 0; i < 8; i++)
        #pragma unroll
        for (int j = 0; j < 8; j++) acc[i][j] = 0.f;

    float4 a0v, a1v, b0v, b1v;
    {
        int r0 = row0 + ar, r1 = row0 + ar + 64;
        a0v = ld4(&P1[(size_t)r0*HD + ak]);
        a1v = ld4(&P1[(size_t)r1*HD + ak]);
        if (P2) { a0v = f4fma(w2/w1, ld4(&P2[(size_t)r0*HD + ak]), a0v);
                  a1v = f4fma(w2/w1, ld4(&P2[(size_t)r1*HD + ak]), a1v); }
        b0v = ld4(&U2[(size_t)bk*HD + col0 + bn]);
        b1v = ld4(&U2[(size_t)(bk+8)*HD + col0 + bn]);
    }
    As[0][ak+0][ar]=a0v.x; As[0][ak+1][ar]=a0v.y; As[0][ak+2][ar]=a0v.z; As[0][ak+3][ar]=a0v.w;
    As[0][ak+0][64+ar]=a1v.x; As[0][ak+1][64+ar]=a1v.y; As[0][ak+2][64+ar]=a1v.z; As[0][ak+3][64+ar]=a1v.w;
    *(float4*)&Bs[0][bk][bn] = b0v; *(float4*)&Bs[0][bk+8][bn] = b1v;
    __syncthreads();

    int buf = 0;
    #pragma unroll 1
    for (int t = 0; t < 16; t++) {
        if (t < 15) {
            int k0 = (t + 1) * 16;
            int r0 = row0 + ar, r1 = row0 + ar + 64;
            a0v = ld4(&P1[(size_t)r0*HD + k0 + ak]);
            a1v = ld4(&P1[(size_t)r1*HD + k0 + ak]);
            if (P2) { a0v = f4fma(w2/w1, ld4(&P2[(size_t)r0*HD + k0 + ak]), a0v);
                      a1v = f4fma(w2/w1, ld4(&P2[(size_t)r1*HD + k0 + ak]), a1v); }
            b0v = ld4(&U2[(size_t)(k0+bk)*HD + col0 + bn]);
            b1v = ld4(&U2[(size_t)(k0+bk+8)*HD + col0 + bn]);
        }
        #pragma unroll
        for (int k = 0; k < 16; k++) {
            float4 pa0 = *(float4*)&As[buf][k][ty*4];
            float4 pa1 = *(float4*)&As[buf][k][64 + ty*4];
            float4 pb0 = *(float4*)&Bs[buf][k][tx*4];
            float4 pb1 = *(float4*)&Bs[buf][k][64 + tx*4];
            float aa[8] = {pa0.x,pa0.y,pa0.z,pa0.w,pa1.x,pa1.y,pa1.z,pa1.w};
            float bb[8] = {pb0.x,pb0.y,pb0.z,pb0.w,pb1.x,pb1.y,pb1.z,pb1.w};
            #pragma unroll
            for (int i = 0; i < 8; i++)
                #pragma unroll
                for (int j = 0; j < 8; j++)
                    acc[i][j] = fmaf(aa[i], bb[j], acc[i][j]);
        }
        if (t < 15) {
            int nb2 = buf ^ 1;
            As[nb2][ak+0][ar]=a0v.x; As[nb2][ak+1][ar]=a0v.y; As[nb2][ak+2][ar]=a0v.z; As[nb2][ak+3][ar]=a0v.w;
            As[nb2][ak+0][64+ar]=a1v.x; As[nb2][ak+1][64+ar]=a1v.y; As[nb2][ak+2][64+ar]=a1v.z; As[nb2][ak+3][64+ar]=a1v.w;
            *(float4*)&Bs[nb2][bk][bn] = b0v; *(float4*)&Bs[nb2][bk+8][bn] = b1v;
        }
        __syncthreads();
        buf ^= 1;
    }

    float sc = w1 * scale;
    #pragma unroll
    for (int ih = 0; ih < 2; ih++)
        #pragma unroll
        for (int ii = 0; ii < 4; ii++) {
            int r = row0 + ih*64 + ty*4 + ii;          // k index
            #pragma unroll
            for (int jh = 0; jh < 2; jh++) {
                int c = col0 + jh*64 + tx*4;           // n index (within 256)
                float vv[4];
                #pragma unroll
                for (int j = 0; j < 4; j++) vv[j] = acc[ih*4+ii][jh*4+j] * sc;
                if (addU1) {
                    float4 u = ld4(&U1[(size_t)r*HD + c]);
                    vv[0]+=u.x; vv[1]+=u.y; vv[2]+=u.z; vv[3]+=u.w;
                }
                if (sec < 3) {
                    #pragma unroll
                    for (int j = 0; j < 4; j++) {
                        int n = sec*HD + c + j;
                        size_t o = ((size_t)lh*NWC + n)*HD + r;
                        __nv_bfloat16 hi = __float2bfloat16(vv[j]);
                        g_wth[o] = hi;
                        g_wtl[o] = __float2bfloat16(vv[j] - __bfloat162float(hi));
                    }
                } else {
                    float4 v = make_float4(vv[0],vv[1],vv[2],vv[3]);
                    *(float4*)&g_We[(size_t)lh*HD*HD + (size_t)r*HD + c] = v;
                }
            }
        }
}

// ---------------- bias folding ----------------
__global__ void bias_kernel(const float* __restrict__ msg_b,
                            const float* __restrict__ upd_w,
                            const float* __restrict__ upd_b) {
    int lh = blockIdx.x; int l = lh >> 1, h = lh & 1;
    int c = threadIdx.x;
    __shared__ float v1[HD], v2[HD];
    float mbh = msg_b[(l*3 + h)*HD + c];
    float mb2 = msg_b[(l*3 + 2)*HD + c];
    v1[c] = 2.f*mbh + mb2;
    v2[c] = mbh + mb2;
    __syncthreads();
    const float* U2 = upd_w + ((size_t)l*512 + HD) * HD;
    float s1 = 0.f, s2 = 0.f;
    for (int k = 0; k < HD; k++) {
        float u = U2[(size_t)k*HD + c];
        s1 += v1[k]*u; s2 += v2[k]*u;
    }
    g_bias [lh*HD + c] = s1*(1.f/3.f) + upd_b[l*HD + c];
    g_bias2[lh*HD + c] = s2*0.5f     + upd_b[l*HD + c];
}

// ---------------- tensor-core GEMM via mma.sync + ldmatrix ---------------
// C[128x128]/CTA; BK=32; 2-stage cp.async (round-6 structure); 2 CTAs/SM.
// 2-product split: Ah@Bh + Ah@Bl. bf16 T output. 80B smem rows.
#define MAT_SZ  10240            // 128 rows * 80 B
#define STG_TOT 30720            // AH | BH | BL
#define SMEM_MMA 67584           // max(2 stages = 61440, C stage 128*132*4)

__global__ __launch_bounds__(256, 2) void gemm_mma(int l) {
    extern __shared__ __align__(16) char sm[];
    uint32_t sb = smem_u32(sm);
    int tid = threadIdx.x, wid = tid >> 5, lane = tid & 31;
    int cb = blockIdx.x, rb = blockIdx.y, half = blockIdx.z;
    int lh = l*2 + half;
    const __nv_bfloat16* Axh = g_xh + (size_t)half*NB*HD;
    const __nv_bfloat16* Bwh = g_wth + (size_t)lh*NWC*HD;
    const __nv_bfloat16* Bwl = g_wtl + (size_t)lh*NWC*HD;

    int lr0 = tid >> 2, lseg = tid & 3;
    int an0 = rb*128 + lr0;      if (an0 >= NB) an0 = NB-1;
    int an1 = rb*128 + lr0 + 64; if (an1 >= NB) an1 = NB-1;
    int bn0 = cb*128 + lr0, bn1 = cb*128 + lr0 + 64;

    #define LOAD_STAGE(s, k0) do {                                             \
        uint32_t d0 = sb + (uint32_t)(s)*STG_TOT + lr0*80 + lseg*16;           \
        uint32_t d1 = d0 + 64*80;                                              \
        size_t ka = (size_t)(k0) + lseg*8;                                     \
        cpa16(d0,            Axh + (size_t)an0*HD + ka);                       \
        cpa16(d1,            Axh + (size_t)an1*HD + ka);                       \
        cpa16(d0 + MAT_SZ,   Bwh + (size_t)bn0*HD + ka);                       \
        cpa16(d1 + MAT_SZ,   Bwh + (size_t)bn1*HD + ka);                       \
        cpa16(d0 + 2*MAT_SZ, Bwl + (size_t)bn0*HD + ka);                       \
        cpa16(d1 + 2*MAT_SZ, Bwl + (size_t)bn1*HD + ka);                       \
        asm volatile("cp.async.commit_group;" ::: "memory");                   \
    } while (0)

    float acc[4][4][4];
    #pragma unroll
    for (int i = 0; i < 4; i++)
        #pragma unroll
        for (int j = 0; j < 4; j++)
            #pragma unroll
            for (int q = 0; q < 4; q++) acc[i][j][q] = 0.f;

    LOAD_STAGE(0, 0);
    LOAD_STAGE(1, 32);

    int warp_m = (wid >> 2) * 64, warp_n = (wid & 3) * 32;
    int la7 = lane & 7, lb8 = (lane >> 3) & 1, lhi = lane >> 4;
    uint32_t aoff = (uint32_t)(warp_m + la7 + lb8*8)*80 + lhi*16;
    uint32_t boff = MAT_SZ + (uint32_t)(warp_n + lhi*8 + la7)*80 + lb8*16;

    #pragma unroll 1
    for (int kt = 0; kt < 8; kt++) {
        if (kt < 7) asm volatile("cp.async.wait_group 1;" ::: "memory");
        else        asm volatile("cp.async.wait_group 0;" ::: "memory");
        __syncthreads();
        uint32_t stg = sb + (uint32_t)(kt & 1) * STG_TOT;
        #pragma unroll
        for (int k16 = 0; k16 < 2; k16++) {
            uint32_t ko = k16 * 32;
            uint32_t ah[4][4];
            #pragma unroll
            for (int i = 0; i < 4; i++)
                LDM4(ah[i], stg + aoff + i*1280 + ko);
            #pragma unroll
            for (int jj = 0; jj < 2; jj++) {
                uint32_t bh[4], bl[4];
                LDM4(bh, stg + boff + jj*1280 + ko);
                LDM4(bl, stg + MAT_SZ + boff + jj*1280 + ko);
                #pragma unroll
                for (int j2 = 0; j2 < 2; j2++) {
                    int j = jj*2 + j2;
                    #pragma unroll
                    for (int i = 0; i < 4; i++) {
                        MMA2(acc[i][j], ah[i], bh[j2*2], bh[j2*2+1]);
                        MMA2(acc[i][j], ah[i], bl[j2*2], bl[j2*2+1]);
                    }
                }
            }
        }
        __syncthreads();
        if (kt + 2 < 8) LOAD_STAGE(kt & 1, (kt + 2) * 32);
    }

    // epilogue: stage C through SMEM (fp32), store bf16 coalesced
    asm volatile("cp.async.wait_group 0;" ::: "memory");
    __syncthreads();
    float* Cs = (float*)sm;                    // 128 x 132 floats
    int g = lane >> 2;
    int ct = (lane & 3) * 2;
    #pragma unroll
    for (int i = 0; i < 4; i++)
        #pragma unroll
        for (int j = 0; j < 4; j++) {
            int r = warp_m + i*16 + g;
            int c = warp_n + j*8 + ct;
            *(float2*)&Cs[(size_t)r*132 + c]      = make_float2(acc[i][j][0], acc[i][j][1]);
            *(float2*)&Cs[(size_t)(r+8)*132 + c]  = make_float2(acc[i][j][2], acc[i][j][3]);
        }
    __syncthreads();
    #pragma unroll
    for (int it = 0; it < 16; it++) {
        int idx = tid + it*256;
        int r = idx >> 5, c4 = (idx & 31) * 4;
        int node = rb*128 + r;
        if (node < NB) {
            float4 v = *(float4*)&Cs[(size_t)r*132 + c4];
            __nv_bfloat162 p0 = __nv_bfloat162(__float2bfloat16(v.x), __float2bfloat16(v.y));
            __nv_bfloat162 p1 = __nv_bfloat162(__float2bfloat16(v.z), __float2bfloat16(v.w));
            uint2 pk;
            pk.x = *(uint32_t*)&p0; pk.y = *(uint32_t*)&p1;
            *(uint2*)&g_T[((size_t)(half*NB + node))*NWC + cb*128 + c4] = pk;
        }
    }
    #undef LOAD_STAGE
}

// ---------------- combine: u-sum + LN + GeLU + residual (h bf16) ----------
__global__ __launch_bounds__(256) void combine(int l,
        const float* __restrict__ ln_g, const float* __restrict__ ln_b) {
    int node = blockIdx.x * 8 + (threadIdx.x >> 5);
    int lane = threadIdx.x & 31;
    int half = node >= NB ? 1 : 0;
    int i = node - half * NB;
    int p = half ? node - NB : node + NB;
    int c0 = lane * 4, c1 = 128 + lane * 4;
    float4 u0, u1;

    if (i > 0 && i < NB - 1) {
        const __nv_bfloat16* tS  = g_T + (size_t)node * NWC;
        const __nv_bfloat16* tNm = g_T + (size_t)(node - 1) * NWC + 256;
        const __nv_bfloat16* tNp = g_T + (size_t)(node + 1) * NWC + 256;
        const __nv_bfloat16* tX  = g_T + (size_t)p * NWC + 512;
        const float* bi  = g_bias + (l*2 + half) * HD;
        u0 = f4add(f4add(ld4bf(tS+c0), ld4bf(tNm+c0)),
                   f4add(ld4bf(tNp+c0), f4add(ld4bf(tX+c0), ld4(bi+c0))));
        u1 = f4add(f4add(ld4bf(tS+c1), ld4bf(tNm+c1)),
                   f4add(ld4bf(tNp+c1), f4add(ld4bf(tX+c1), ld4(bi+c1))));
    } else {
        int nn = (i == 0) ? node + 1 : node - 1;
        const float* E  = g_We + (size_t)(l*2 + half) * HD * HD;
        const __nv_bfloat16* xg = g_xh + (size_t)node * HD;
        float4 s0 = f4z(), s1 = f4z();
        #pragma unroll 4
        for (int k = 0; k < HD; k++) {
            float xv = __bfloat162float(xg[k]);
            s0 = f4fma(xv, ld4(&E[(size_t)k*HD + c0]), s0);
            s1 = f4fma(xv, ld4(&E[(size_t)k*HD + c1]), s1);
        }
        const __nv_bfloat16* tN = g_T + (size_t)nn * NWC + 256;
        const __nv_bfloat16* tX = g_T + (size_t)p * NWC + 512;
        const float* bi2 = g_bias2 + (l*2 + half) * HD;
        u0 = f4add(s0, f4fma(1.5f, f4add(ld4bf(tN+c0), ld4bf(tX+c0)), ld4(bi2+c0)));
        u1 = f4add(s1, f4fma(1.5f, f4add(ld4bf(tN+c1), ld4bf(tX+c1)), ld4(bi2+c1)));
    }

    float s = u0.x+u0.y+u0.z+u0.w + u1.x+u1.y+u1.z+u1.w;
    float q = u0.x*u0.x+u0.y*u0.y+u0.z*u0.z+u0.w*u0.w
            + u1.x*u1.x+u1.y*u1.y+u1.z*u1.z+u1.w*u1.w;
    #pragma unroll
    for (int off = 16; off; off >>= 1) {
        s += __shfl_xor_sync(0xffffffff, s, off);
        q += __shfl_xor_sync(0xffffffff, q, off);
    }
    float mu = s * (1.f/HD);
    float rs = rsqrtf(q * (1.f/HD) - mu*mu + 1e-5f);

    const float* lg = ln_g + l*HD;
    const float* lb = ln_b + l*HD;
    float4 g0 = ld4(lg+c0), g1 = ld4(lg+c1);
    float4 b0 = ld4(lb+c0), b1 = ld4(lb+c1);
    size_t ho = (size_t)node * HD;
    float4 h0 = ld4bf(&g_xh[ho+c0]), h1 = ld4bf(&g_xh[ho+c1]);
    h0.x += gelu_exact((u0.x-mu)*rs*g0.x + b0.x);
    h0.y += gelu_exact((u0.y-mu)*rs*g0.y + b0.y);
    h0.z += gelu_exact((u0.z-mu)*rs*g0.z + b0.z);
    h0.w += gelu_exact((u0.w-mu)*rs*g0.w + b0.w);
    h1.x += gelu_exact((u1.x-mu)*rs*g1.x + b1.x);
    h1.y += gelu_exact((u1.y-mu)*rs*g1.y + b1.y);
    h1.z += gelu_exact((u1.z-mu)*rs*g1.z + b1.z);
    h1.w += gelu_exact((u1.w-mu)*rs*g1.w + b1.w);
    st_hi(ho+c0, h0);
    st_hi(ho+c1, h1);
}

// ---------------- readout ----------------
__global__ void zero_hm() { if (threadIdx.x < HD) g_hm[threadIdx.x] = 0.f; }

__global__ void colmean() {
    int c = threadIdx.x;
    int r0 = blockIdx.x * 200;
    float s = 0.f;
    for (int r = r0; r < r0 + 200; r++)
        s += __bfloat162float(g_xh[(size_t)r * HD + c]);
    atomicAdd(&g_hm[c], s);
}

__global__ void decoder(const float* __restrict__ dec1_w, const float* __restrict__ dec1_b,
                        const float* __restrict__ dec2_w, const float* __restrict__ dec2_b,
                        const float* __restrict__ Kp, const float* __restrict__ tau,
                        const float* __restrict__ tau_max, const float* __restrict__ lam,
                        float* __restrict__ out) {
    __shared__ float hm[HD], z[HD], red[64];
    int t = threadIdx.x;
    hm[t] = g_hm[t] * (1.0f / NB);
    __syncthreads();
    float acc = dec1_b[t];
    for (int k = 0; k < HD; k++) acc += hm[k] * dec1_w[k * HD + t];
    z[t] = gelu_exact(acc);
    __syncthreads();
    if (t < 128) {
        float a = dec2_b[t];
        for (int k = 0; k < HD; k++) a += z[k] * dec2_w[k * 128 + t];
        out[t] = a;
    }
    if (t < 64) {
        red[t] = Kp[t] * tau[t] / tau_max[t];
        out[129 + t] = Kp[t];
    }
    __syncthreads();
    if (t == 0) {
        float s = 0.f;
        for (int i = 0; i < 64; i++) s += red[i];
        out[128] = fabsf(lam[0]) - s;
    }
}

// ---------------- launch ----------------
extern "C" void kernel_launch(void* const* d_in, const int* in_sizes, int n_in,
                              void* d_out, int out_size) {
    const float* energy_x     = (const float*)d_in[0];
    const float* comm_x       = (const float*)d_in[1];
    const float* tau          = (const float*)d_in[2];
    const float* tau_max      = (const float*)d_in[3];
    const float* lambda_min_0 = (const float*)d_in[4];
    const float* We_w         = (const float*)d_in[5];
    const float* We_b         = (const float*)d_in[6];
    const float* Wc_w         = (const float*)d_in[7];
    const float* Wc_b         = (const float*)d_in[8];
    const float* msg_w        = (const float*)d_in[9];
    const float* msg_b        = (const float*)d_in[10];
    const float* upd_w        = (const float*)d_in[11];
    const float* upd_b        = (const float*)d_in[12];
    const float* ln_g         = (const float*)d_in[13];
    const float* ln_b         = (const float*)d_in[14];
    const float* dec1_w       = (const float*)d_in[15];
    const float* dec1_b       = (const float*)d_in[16];
    const float* dec2_w       = (const float*)d_in[17];
    const float* dec2_b       = (const float*)d_in[18];
    const float* K_param      = (const float*)d_in[19];
    float* out = (float*)d_out;

    cudaFuncSetAttribute(gemm_mma, cudaFuncAttributeMaxDynamicSharedMemorySize, SMEM_MMA);

    gemm_pre<<<dim3(8, 2, 8), 256>>>(msg_w, upd_w);
    bias_kernel<<<8, 256>>>(msg_b, upd_w, upd_b);
    encode<<<(TWO_N * HD / 4 + 255) / 256, 256>>>(energy_x, comm_x, We_w, We_b, Wc_w, Wc_b);

    for (int l = 0; l < NL; l++) {
        gemm_mma<<<dim3(6, (NB + 127) / 128, 2), 256, SMEM_MMA>>>(l);
        combine<<<TWO_N / 8, 256>>>(l, ln_g, ln_b);
    }

    zero_hm<<<1, 256>>>();
    colmean<<<100, 256>>>();
    decoder<<<1, 256>>>(dec1_w, dec1_b, dec2_w, dec2_b,
                        K_param, tau, tau_max, lambda_min_0, out);
}